// round 6
// baseline (speedup 1.0000x reference)
#include <cuda_runtime.h>
#include <cuda_bf16.h>
#include <stdint.h>

// ---------------- problem constants (fixed shapes) ----------------
#define BATCH 256
#define TT    250
#define CC    700
#define KP    704          // C padded to multiple of 32
#define H1    1024
#define H2    512
#define OO    20
#define BT    (BATCH*TT)   // 64000

// ---------------- device scratch ----------------
static __device__ __nv_bfloat16 g_xd[(size_t)BT * KP];    // delayed input bf16 [r][k], 90MB
static __device__ __nv_bfloat16 g_WinB[H1 * KP];          // W_in bf16 [h][k], zero-padded k
static __device__ __nv_bfloat16 g_IinB[(size_t)BT * H1];  // I_in bf16 [r][h], 131MB
static __device__ float g_Wr1T[H1 * H1];                  // [j][h]
static __device__ float g_W2T[H1 * H2];                   // [j1][h2]
static __device__ float g_Wr2T[H2 * H2];                  // [j2][h2]
static __device__ float g_WoT[H2 * OO];                   // [j2][o]

// ---------------- K1: weight prep ----------------
__global__ void k_prep(const float* __restrict__ Win, const float* __restrict__ Wr1,
                       const float* __restrict__ W2, const float* __restrict__ Wr2,
                       const float* __restrict__ Wo)
{
    const int N0 = H1 * KP;
    const int N1 = H1 * H1;
    const int N2 = H1 * H2;
    const int N3 = H2 * H2;
    const int N4 = H2 * OO;
    const int total = N0 + N1 + N2 + N3 + N4;
    for (int i = blockIdx.x * blockDim.x + threadIdx.x; i < total; i += gridDim.x * blockDim.x) {
        int r = i;
        if (r < N0) {
            int h = r / KP, k = r % KP;
            g_WinB[r] = __float2bfloat16((k < CC) ? Win[h * CC + k] : 0.0f);
            continue;
        }
        r -= N0;
        if (r < N1) { int j = r / H1, h = r % H1; g_Wr1T[r] = Wr1[h * H1 + j]; continue; }
        r -= N1;
        if (r < N2) { int j = r / H2, h = r % H2; g_W2T[r] = W2[h * H1 + j]; continue; }
        r -= N2;
        if (r < N3) { int j = r / H2, h = r % H2; g_Wr2T[r] = Wr2[h * H2 + j]; continue; }
        r -= N3;
        { int j = r / OO, o = r % OO; g_WoT[r] = Wo[o * H2 + j]; }
    }
}

// ---------------- K2: build delayed input (125-step t-tiles) ----------------
__global__ void k_build_xd(const float* __restrict__ x, const int* __restrict__ delays)
{
    __shared__ float stage[185][32];
    __shared__ int dsh[KP];
    const int b  = blockIdx.y;
    const int t0 = blockIdx.x * 125;
    const int tx = threadIdx.x, ty = threadIdx.y;
    const int tid = ty * 32 + tx;
    for (int i = tid; i < KP; i += 1024) dsh[i] = (i < CC) ? delays[i] : 0;

    for (int c0 = 0; c0 < KP; c0 += 32) {
        __syncthreads();
        for (int idx = tid; idx < 185 * 32; idx += 1024) {
            int r = idx >> 5;
            int c = c0 + (idx & 31);
            int tg = t0 - 60 + r;
            float v = 0.0f;
            if (tg >= 0 && tg < TT && c < CC) v = x[((size_t)b * TT + tg) * CC + c];
            stage[r][idx & 31] = v;
        }
        __syncthreads();
        const int c = c0 + tx;
        const int d = dsh[c];
        for (int tt = ty; tt < 125; tt += 32) {
            float v = (c < CC) ? stage[tt + 60 - d][tx] : 0.0f;
            g_xd[((size_t)b * TT + t0 + tt) * KP + c] = __float2bfloat16(v);
        }
    }
}

// ---------------- K3: bf16 HMMA GEMM, 128x256 tile, warp tile 64x64 ----------------
#define BM 128
#define BN 256
#define BKK 32
#define SMSTR 40   // bf16 row stride (80B): 16B aligned, ldmatrix conflict-free
#define ASTG (BM * SMSTR)
#define BSTG (BN * SMSTR)
#define GEMM_SMEM (3 * (ASTG + BSTG) * 2)   // 92160 bytes

#define CP_ASYNC16(dst_u32, src_ptr) \
    asm volatile("cp.async.cg.shared.global [%0], [%1], 16;\n" :: "r"(dst_u32), "l"(src_ptr))
#define CP_COMMIT() asm volatile("cp.async.commit_group;\n" ::)
#define CP_WAIT1()  asm volatile("cp.async.wait_group 1;\n" ::)

__global__ void __launch_bounds__(256, 1) k_gemm()
{
    extern __shared__ __nv_bfloat16 smem[];
    __nv_bfloat16* Abase = smem;                 // 3 stages of ASTG
    __nv_bfloat16* Bbase = smem + 3 * ASTG;      // 3 stages of BSTG

    const int tid    = threadIdx.x;
    const int warpId = tid >> 5;
    const int lane   = tid & 31;
    const int g      = lane >> 2;
    const int t4     = lane & 3;

    const int row0 = blockIdx.y * BM;
    const int col0 = blockIdx.x * BN;
    const int wm   = (warpId & 1) * 64;
    const int wn   = (warpId >> 1) * 64;

    const __nv_bfloat16* Ag = g_xd   + (size_t)row0 * KP;
    const __nv_bfloat16* Bg = g_WinB + (size_t)col0 * KP;

    uint32_t sA[3], sB[3];
#pragma unroll
    for (int s = 0; s < 3; ++s) {
        sA[s] = (uint32_t)__cvta_generic_to_shared(Abase + s * ASTG);
        sB[s] = (uint32_t)__cvta_generic_to_shared(Bbase + s * BSTG);
    }

    // ldmatrix lane base offsets (bytes)
    const int aoff = ((wm + (lane & 15)) * SMSTR + (lane >> 4) * 8) * 2;
    const int boff = ((wn + (lane & 7) + ((lane >> 4) << 3)) * SMSTR + ((lane >> 3) & 1) * 8) * 2;

    float acc[4][8][4];
#pragma unroll
    for (int i = 0; i < 4; ++i)
#pragma unroll
        for (int j = 0; j < 8; ++j)
#pragma unroll
            for (int c = 0; c < 4; ++c) acc[i][j][c] = 0.0f;

    // stage fill: A = 128x32 (512 x 16B chunks), B = 256x32 (1024 chunks)
    auto fill = [&](int s, int k0) {
#pragma unroll
        for (int i = 0; i < 2; ++i) {
            const int cid = tid + i * 256;
            const int r = cid >> 2, c = cid & 3;
            CP_ASYNC16(sA[s] + (r * SMSTR + c * 8) * 2, Ag + (size_t)r * KP + k0 + c * 8);
        }
#pragma unroll
        for (int i = 0; i < 4; ++i) {
            const int cid = tid + i * 256;
            const int r = cid >> 2, c = cid & 3;
            CP_ASYNC16(sB[s] + (r * SMSTR + c * 8) * 2, Bg + (size_t)r * KP + k0 + c * 8);
        }
    };

    const int NK = KP / BKK;   // 22

#pragma unroll
    for (int s = 0; s < 2; ++s) { fill(s, s * BKK); CP_COMMIT(); }

    int st = 0;
    for (int kt = 0; kt < NK; ++kt) {
        CP_WAIT1();
        __syncthreads();

        if (kt + 2 < NK) {
            const int s = (st + 2 >= 3) ? st - 1 : st + 2;   // (kt+2)%3
            fill(s, (kt + 2) * BKK);
        }
        CP_COMMIT();

        const uint32_t aBase = sA[st] + aoff;
        const uint32_t bBase = sB[st] + boff;
#pragma unroll
        for (int ks = 0; ks < BKK; ks += 16) {
            uint32_t af[4][4];
            uint32_t bq[4][4];
#pragma unroll
            for (int i = 0; i < 4; ++i) {
                asm volatile("ldmatrix.sync.aligned.m8n8.x4.shared.b16 {%0,%1,%2,%3}, [%4];"
                             : "=r"(af[i][0]), "=r"(af[i][1]), "=r"(af[i][2]), "=r"(af[i][3])
                             : "r"(aBase + (i * 16 * SMSTR + ks) * 2));
            }
#pragma unroll
            for (int j2 = 0; j2 < 4; ++j2) {
                asm volatile("ldmatrix.sync.aligned.m8n8.x4.shared.b16 {%0,%1,%2,%3}, [%4];"
                             : "=r"(bq[j2][0]), "=r"(bq[j2][1]), "=r"(bq[j2][2]), "=r"(bq[j2][3])
                             : "r"(bBase + (j2 * 16 * SMSTR + ks) * 2));
            }
#pragma unroll
            for (int i = 0; i < 4; ++i)
#pragma unroll
                for (int j = 0; j < 8; ++j) {
                    const uint32_t b0 = bq[j >> 1][(j & 1) * 2];
                    const uint32_t b1 = bq[j >> 1][(j & 1) * 2 + 1];
                    asm volatile(
                        "mma.sync.aligned.m16n8k16.row.col.f32.bf16.bf16.f32 "
                        "{%0,%1,%2,%3}, {%4,%5,%6,%7}, {%8,%9}, {%0,%1,%2,%3};\n"
                        : "+f"(acc[i][j][0]), "+f"(acc[i][j][1]),
                          "+f"(acc[i][j][2]), "+f"(acc[i][j][3])
                        : "r"(af[i][0]), "r"(af[i][1]), "r"(af[i][2]), "r"(af[i][3]),
                          "r"(b0), "r"(b1));
                }
        }
        st = (st + 1 == 3) ? 0 : st + 1;
    }

    // epilogue: bf16 pairs
#pragma unroll
    for (int i = 0; i < 4; ++i) {
#pragma unroll
        for (int j = 0; j < 8; ++j) {
            const int r0 = row0 + wm + i * 16 + g;
            const int c  = col0 + wn + j * 8 + 2 * t4;
            __nv_bfloat162 p0 = __float22bfloat162_rn(make_float2(acc[i][j][0], acc[i][j][1]));
            __nv_bfloat162 p1 = __float22bfloat162_rn(make_float2(acc[i][j][2], acc[i][j][3]));
            *reinterpret_cast<__nv_bfloat162*>(&g_IinB[(size_t)r0 * H1 + c])       = p0;
            *reinterpret_cast<__nv_bfloat162*>(&g_IinB[(size_t)(r0 + 8) * H1 + c]) = p1;
        }
    }
}

// ---------------- K4: recurrent scan — 2 batches per CTA, 2 barriers/step ----------------
__global__ void __launch_bounds__(1024, 1) k_scan(
    const float* __restrict__ alpha1, const float* __restrict__ rho1, const float* __restrict__ beta_a1,
    const float* __restrict__ alpha2, const float* __restrict__ rho2, const float* __restrict__ beta_a2,
    const float* __restrict__ beta_out, float* __restrict__ out)
{
    __shared__ int cnt1[2][2], cnt2[2][2];
    __shared__ int act1[2][2][H1];
    __shared__ int act2[2][2][H2];

    const int tid  = threadIdx.x;
    const int sub  = tid >> 9;          // which batch of the pair
    const int stid = tid & 511;
    const int b    = blockIdx.x * 2 + sub;
    const int h0   = 2 * stid;

    const float2 al1 = *(const float2*)&alpha1[h0];
    const float2 r1  = *(const float2*)&rho1[h0];
    const float2 ba1 = *(const float2*)&beta_a1[h0];
    float v1x = 0.f, v1y = 0.f, a1x = 0.f, a1y = 0.f, s1x = 0.f, s1y = 0.f;

    float2 al2 = make_float2(0.f, 0.f), r2 = al2, ba2 = al2;
    float v2x = 0.f, v2y = 0.f, a2x = 0.f, a2y = 0.f, s2x = 0.f, s2y = 0.f;
    if (stid < H2 / 2) {
        al2 = *(const float2*)&alpha2[h0];
        r2  = *(const float2*)&rho2[h0];
        ba2 = *(const float2*)&beta_a2[h0];
    }

    float bo = 0.f, obo = 0.f, vo = 0.f, vos = 0.f;
    if (stid < OO) { bo = beta_out[stid]; obo = 1.0f - bo; }

    if (stid == 0) {
        cnt1[sub][0] = cnt1[sub][1] = 0;
        cnt2[sub][0] = cnt2[sub][1] = 0;
    }
    __syncthreads();

    const uint32_t* Ib = reinterpret_cast<const uint32_t*>(g_IinB + (size_t)b * TT * H1) + stid;
    uint32_t buf0 = Ib[0 * (H1 / 2)];
    uint32_t buf1 = Ib[1 * (H1 / 2)];
    uint32_t buf2 = Ib[2 * (H1 / 2)];
    uint32_t buf3 = Ib[3 * (H1 / 2)];
    int p = 0;

    auto step = [&](uint32_t packed, uint32_t& slot, int tn, int t) {
        const __nv_bfloat162 bp = *reinterpret_cast<const __nv_bfloat162*>(&packed);
        float I1x = __low2float(bp);
        float I1y = __high2float(bp);
        if (tn < TT) slot = Ib[(size_t)tn * (H1 / 2)];   // prefetch 4 ahead

        const int q = p ^ 1;
        // ---- phase A: layer-1 update (reads act1[p]); reset cnt1[q]
        if (stid == 0) cnt1[sub][q] = 0;
        const int n1 = cnt1[sub][p];
        for (int i = 0; i < n1; ++i) {
            const float2 w = *(const float2*)&g_Wr1T[act1[sub][p][i] * H1 + h0];
            I1x += w.x; I1y += w.y;
        }
        v1x = al1.x * v1x + (1.0f - al1.x) * I1x - s1x - a1x;
        v1y = al1.y * v1y + (1.0f - al1.y) * I1y - s1y - a1y;
        const float ns1x = (v1x >= 1.0f) ? 1.0f : 0.0f;
        const float ns1y = (v1y >= 1.0f) ? 1.0f : 0.0f;
        a1x = r1.x * a1x + ba1.x * ns1x;
        a1y = r1.y * a1y + ba1.y * ns1y;
        s1x = ns1x; s1y = ns1y;
        __syncthreads();                                 // B1

        // ---- phase B: publish layer-1 spikes; reset cnt2[q]
        if (stid == 1) cnt2[sub][q] = 0;
        if (ns1x != 0.0f) { int idx = atomicAdd(&cnt1[sub][q], 1); act1[sub][q][idx] = h0; }
        if (ns1y != 0.0f) { int idx = atomicAdd(&cnt1[sub][q], 1); act1[sub][q][idx] = h0 + 1; }
        __syncthreads();                                 // B2

        // ---- phase C: layer-2 update + deferred readout of step t-1
        if (stid < H2 / 2) {
            float I2x = 0.f, I2y = 0.f;
            const int m1 = cnt1[sub][q];
            for (int i = 0; i < m1; ++i) {
                const float2 w = *(const float2*)&g_W2T[act1[sub][q][i] * H2 + h0];
                I2x += w.x; I2y += w.y;
            }
            const int n2 = cnt2[sub][p];
            for (int i = 0; i < n2; ++i) {
                const float2 w = *(const float2*)&g_Wr2T[act2[sub][p][i] * H2 + h0];
                I2x += w.x; I2y += w.y;
            }
            v2x = al2.x * v2x + (1.0f - al2.x) * I2x - s2x - a2x;
            v2y = al2.y * v2y + (1.0f - al2.y) * I2y - s2y - a2y;
            const float ns2x = (v2x >= 1.0f) ? 1.0f : 0.0f;
            const float ns2y = (v2y >= 1.0f) ? 1.0f : 0.0f;
            a2x = r2.x * a2x + ba2.x * ns2x;
            a2y = r2.y * a2y + ba2.y * ns2y;
            s2x = ns2x; s2y = ns2y;
            if (ns2x != 0.0f) { int idx = atomicAdd(&cnt2[sub][q], 1); act2[sub][q][idx] = h0; }
            if (ns2y != 0.0f) { int idx = atomicAdd(&cnt2[sub][q], 1); act2[sub][q][idx] = h0 + 1; }
        }
        if (stid < OO && t > 0) {
            // readout for step t-1: reads act2[sub][p] (stable through this phase)
            float Io = 0.f;
            const int m2 = cnt2[sub][p];
            for (int i = 0; i < m2; ++i) Io += g_WoT[act2[sub][p][i] * OO + stid];
            vo = bo * vo + obo * Io;
            vos += vo;
        }
        p = q;
    };

    for (int t = 0; t < 248; t += 4) {
        step(buf0, buf0, t + 4, t);
        step(buf1, buf1, t + 5, t + 1);
        step(buf2, buf2, t + 6, t + 2);
        step(buf3, buf3, t + 7, t + 3);
    }
    step(buf0, buf0, TT, 248);
    step(buf1, buf1, TT, 249);

    __syncthreads();   // final act2 list complete
    if (stid < OO) {
        float Io = 0.f;
        const int m2 = cnt2[sub][p];
        for (int i = 0; i < m2; ++i) Io += g_WoT[act2[sub][p][i] * OO + stid];
        vo = bo * vo + obo * Io;
        vos += vo;
        out[b * OO + stid] = vos * (1.0f / (float)TT);
    }
}

// ---------------- launch ----------------
extern "C" void kernel_launch(void* const* d_in, const int* in_sizes, int n_in,
                              void* d_out, int out_size)
{
    const float* x       = (const float*)d_in[0];
    const int*   delays  = (const int*)  d_in[1];
    const float* W_in    = (const float*)d_in[2];
    const float* W_rec1  = (const float*)d_in[3];
    const float* W2      = (const float*)d_in[4];
    const float* W_rec2  = (const float*)d_in[5];
    const float* W_out   = (const float*)d_in[6];
    const float* alpha1  = (const float*)d_in[7];
    const float* rho1    = (const float*)d_in[8];
    const float* beta_a1 = (const float*)d_in[9];
    const float* alpha2  = (const float*)d_in[10];
    const float* rho2    = (const float*)d_in[11];
    const float* beta_a2 = (const float*)d_in[12];
    const float* beta_out= (const float*)d_in[13];
    float* out = (float*)d_out;

    static int smem_set = 0;
    if (!smem_set) {
        cudaFuncSetAttribute(k_gemm, cudaFuncAttributeMaxDynamicSharedMemorySize, GEMM_SMEM);
        smem_set = 1;
    }

    k_prep<<<2560, 1024>>>(W_in, W_rec1, W2, W_rec2, W_out);

    {
        dim3 grid(2, BATCH);
        dim3 block(32, 32);
        k_build_xd<<<grid, block>>>(x, delays);
    }

    {
        dim3 grid(H1 / BN, BT / BM);   // (4, 500)
        k_gemm<<<grid, 256, GEMM_SMEM>>>();
    }

    k_scan<<<BATCH / 2, 1024>>>(alpha1, rho1, beta_a1, alpha2, rho2, beta_a2, beta_out, out);
}

// round 7
// speedup vs baseline: 1.0160x; 1.0160x over previous
#include <cuda_runtime.h>
#include <cuda_bf16.h>
#include <stdint.h>

// ---------------- problem constants (fixed shapes) ----------------
#define BATCH 256
#define TT    250
#define CC    700
#define KP    704          // C padded to multiple of 32
#define H1    1024
#define H2    512
#define OO    20
#define BT    (BATCH*TT)   // 64000

// ---------------- device scratch ----------------
static __device__ __nv_bfloat16 g_xd[(size_t)BT * KP];    // delayed input bf16 [r][k], 90MB
static __device__ __nv_bfloat16 g_WinB[H1 * KP];          // W_in bf16 [h][k], zero-padded k
static __device__ __nv_bfloat16 g_IinB[(size_t)BT * H1];  // I_in bf16 [r][h], 131MB
static __device__ float g_Wr1T[H1 * H1];                  // [j][h]
static __device__ float g_W2T[H1 * H2];                   // [j1][h2]
static __device__ float g_Wr2T[H2 * H2];                  // [j2][h2]
static __device__ float g_WoT[H2 * OO];                   // [j2][o]

// ---------------- K1: fused prep (delay-build + coalesced transposes) ----------------
// block ranges:
//  [0,512)        : build_xd   (b = idx/2, t0 = (idx%2)*125)
//  [512,576)      : WinB bf16 convert (grid-stride)
//  [576,1600)     : Wr1 transpose, 32x32 tiles (32x32 tile grid)
//  [1600,2112)    : W2 transpose  (16 h-tiles x 32 j-tiles)
//  [2112,2368)    : Wr2 transpose (16x16 tiles)
//  [2368]         : WoT (small, naive)
#define PB_TOTAL 2369

__global__ void __launch_bounds__(1024) k_prep_build(
    const float* __restrict__ x, const int* __restrict__ delays,
    const float* __restrict__ Win, const float* __restrict__ Wr1,
    const float* __restrict__ W2, const float* __restrict__ Wr2,
    const float* __restrict__ Wo)
{
    __shared__ float stage[185][32];
    __shared__ int dsh[KP];
    __shared__ float tile[32][33];

    const int blk = blockIdx.x;
    const int tid = threadIdx.x;
    const int tx = tid & 31, ty = tid >> 5;

    if (blk < 512) {
        // ----- build_xd -----
        const int b  = blk >> 1;
        const int t0 = (blk & 1) * 125;
        for (int i = tid; i < KP; i += 1024) dsh[i] = (i < CC) ? delays[i] : 0;

        for (int c0 = 0; c0 < KP; c0 += 32) {
            __syncthreads();
            for (int idx = tid; idx < 185 * 32; idx += 1024) {
                int r = idx >> 5;
                int c = c0 + (idx & 31);
                int tg = t0 - 60 + r;
                float v = 0.0f;
                if (tg >= 0 && tg < TT && c < CC) v = x[((size_t)b * TT + tg) * CC + c];
                stage[r][idx & 31] = v;
            }
            __syncthreads();
            const int c = c0 + tx;
            const int d = dsh[c];
            for (int tt = ty; tt < 125; tt += 32) {
                float v = (c < CC) ? stage[tt + 60 - d][tx] : 0.0f;
                g_xd[((size_t)b * TT + t0 + tt) * KP + c] = __float2bfloat16(v);
            }
        }
    } else if (blk < 576) {
        // ----- WinB convert (coalesced both sides) -----
        const int N0 = H1 * KP;
        for (int i = (blk - 512) * 1024 + tid; i < N0; i += 64 * 1024) {
            int h = i / KP, k = i % KP;
            g_WinB[i] = __float2bfloat16((k < CC) ? Win[h * CC + k] : 0.0f);
        }
    } else if (blk < 1600) {
        // ----- Wr1T[j][h] = Wr1[h][j], 1024x1024, 32x32 tiles -----
        const int tI = blk - 576;
        const int tr = tI >> 5, tc = tI & 31;      // h-tile, j-tile
        tile[ty][tx] = Wr1[(tr * 32 + ty) * H1 + tc * 32 + tx];
        __syncthreads();
        g_Wr1T[(tc * 32 + ty) * H1 + tr * 32 + tx] = tile[tx][ty];
    } else if (blk < 2112) {
        // ----- W2T[j][h2] = W2[h2][j], W2 is 512x1024 -----
        const int tI = blk - 1600;
        const int th = tI & 15, tj = tI >> 4;      // h-tile (16), j-tile (32)
        tile[ty][tx] = W2[(th * 32 + ty) * H1 + tj * 32 + tx];
        __syncthreads();
        g_W2T[(tj * 32 + ty) * H2 + th * 32 + tx] = tile[tx][ty];
    } else if (blk < 2368) {
        // ----- Wr2T, 512x512 -----
        const int tI = blk - 2112;
        const int tr = tI >> 4, tc = tI & 15;
        tile[ty][tx] = Wr2[(tr * 32 + ty) * H2 + tc * 32 + tx];
        __syncthreads();
        g_Wr2T[(tc * 32 + ty) * H2 + tr * 32 + tx] = tile[tx][ty];
    } else {
        // ----- WoT (512x20, small) -----
        for (int i = tid; i < H2 * OO; i += 1024) {
            int j = i / OO, o = i % OO;
            g_WoT[i] = Wo[o * H2 + j];
        }
    }
}

// ---------------- K3: bf16 HMMA GEMM (R4-proven config) ----------------
#define BM 128
#define BN 128
#define BKK 32
#define SMSTR 40   // bf16 row stride (80B): 16B aligned, ldmatrix conflict-free
#define GEMM_SMEM (3 * (BM + BN) * SMSTR * 2)   // 61440 bytes

#define CP_ASYNC16(dst_u32, src_ptr) \
    asm volatile("cp.async.cg.shared.global [%0], [%1], 16;\n" :: "r"(dst_u32), "l"(src_ptr))
#define CP_COMMIT() asm volatile("cp.async.commit_group;\n" ::)
#define CP_WAIT1()  asm volatile("cp.async.wait_group 1;\n" ::)

__global__ void __launch_bounds__(256) k_gemm()
{
    extern __shared__ __nv_bfloat16 smem[];
    __nv_bfloat16* Abase = smem;
    __nv_bfloat16* Bbase = smem + 3 * BM * SMSTR;

    const int tid    = threadIdx.x;
    const int warpId = tid >> 5;
    const int lane   = tid & 31;
    const int g      = lane >> 2;
    const int t4     = lane & 3;

    const int row0 = blockIdx.y * BM;
    const int col0 = blockIdx.x * BN;
    const int wm   = (warpId & 1) * 64;
    const int wn   = (warpId >> 1) * 32;

    const int lrow0 = tid >> 2;
    const int lseg  = (tid & 3) * 8;

    const __nv_bfloat16* Ag = g_xd   + (size_t)row0 * KP;
    const __nv_bfloat16* Bg = g_WinB + (size_t)col0 * KP;

    uint32_t sA[3], sB[3];
#pragma unroll
    for (int s = 0; s < 3; ++s) {
        sA[s] = (uint32_t)__cvta_generic_to_shared(Abase + s * BM * SMSTR);
        sB[s] = (uint32_t)__cvta_generic_to_shared(Bbase + s * BN * SMSTR);
    }

    const int aoff = ((wm + (lane & 15)) * SMSTR + (lane >> 4) * 8) * 2;
    const int boff = ((wn + (lane & 7) + ((lane >> 4) << 3)) * SMSTR + ((lane >> 3) & 1) * 8) * 2;

    float acc[4][4][4];
#pragma unroll
    for (int i = 0; i < 4; ++i)
#pragma unroll
        for (int j = 0; j < 4; ++j)
#pragma unroll
            for (int c = 0; c < 4; ++c) acc[i][j][c] = 0.0f;

    const int NK = KP / BKK;   // 22

#pragma unroll
    for (int s = 0; s < 2; ++s) {
        const int k0 = s * BKK;
        CP_ASYNC16(sA[s] + (lrow0 * SMSTR + lseg) * 2,        Ag + (size_t)lrow0 * KP + k0 + lseg);
        CP_ASYNC16(sA[s] + ((lrow0 + 64) * SMSTR + lseg) * 2, Ag + (size_t)(lrow0 + 64) * KP + k0 + lseg);
        CP_ASYNC16(sB[s] + (lrow0 * SMSTR + lseg) * 2,        Bg + (size_t)lrow0 * KP + k0 + lseg);
        CP_ASYNC16(sB[s] + ((lrow0 + 64) * SMSTR + lseg) * 2, Bg + (size_t)(lrow0 + 64) * KP + k0 + lseg);
        CP_COMMIT();
    }

    int st = 0;
    for (int kt = 0; kt < NK; ++kt) {
        CP_WAIT1();
        __syncthreads();

        if (kt + 2 < NK) {
            const int s = (st + 2 >= 3) ? st - 1 : st + 2;
            const int k0 = (kt + 2) * BKK;
            CP_ASYNC16(sA[s] + (lrow0 * SMSTR + lseg) * 2,        Ag + (size_t)lrow0 * KP + k0 + lseg);
            CP_ASYNC16(sA[s] + ((lrow0 + 64) * SMSTR + lseg) * 2, Ag + (size_t)(lrow0 + 64) * KP + k0 + lseg);
            CP_ASYNC16(sB[s] + (lrow0 * SMSTR + lseg) * 2,        Bg + (size_t)lrow0 * KP + k0 + lseg);
            CP_ASYNC16(sB[s] + ((lrow0 + 64) * SMSTR + lseg) * 2, Bg + (size_t)(lrow0 + 64) * KP + k0 + lseg);
        }
        CP_COMMIT();

        const uint32_t aBase = sA[st] + aoff;
        const uint32_t bBase = sB[st] + boff;
#pragma unroll
        for (int ks = 0; ks < BKK; ks += 16) {
            uint32_t af[4][4];
            uint32_t bq[2][4];
#pragma unroll
            for (int i = 0; i < 4; ++i) {
                asm volatile("ldmatrix.sync.aligned.m8n8.x4.shared.b16 {%0,%1,%2,%3}, [%4];"
                             : "=r"(af[i][0]), "=r"(af[i][1]), "=r"(af[i][2]), "=r"(af[i][3])
                             : "r"(aBase + (i * 16 * SMSTR + ks) * 2));
            }
#pragma unroll
            for (int j2 = 0; j2 < 2; ++j2) {
                asm volatile("ldmatrix.sync.aligned.m8n8.x4.shared.b16 {%0,%1,%2,%3}, [%4];"
                             : "=r"(bq[j2][0]), "=r"(bq[j2][1]), "=r"(bq[j2][2]), "=r"(bq[j2][3])
                             : "r"(bBase + (j2 * 16 * SMSTR + ks) * 2));
            }
#pragma unroll
            for (int i = 0; i < 4; ++i)
#pragma unroll
                for (int j = 0; j < 4; ++j) {
                    const uint32_t b0 = bq[j >> 1][(j & 1) * 2];
                    const uint32_t b1 = bq[j >> 1][(j & 1) * 2 + 1];
                    asm volatile(
                        "mma.sync.aligned.m16n8k16.row.col.f32.bf16.bf16.f32 "
                        "{%0,%1,%2,%3}, {%4,%5,%6,%7}, {%8,%9}, {%0,%1,%2,%3};\n"
                        : "+f"(acc[i][j][0]), "+f"(acc[i][j][1]),
                          "+f"(acc[i][j][2]), "+f"(acc[i][j][3])
                        : "r"(af[i][0]), "r"(af[i][1]), "r"(af[i][2]), "r"(af[i][3]),
                          "r"(b0), "r"(b1));
                }
        }
        st = (st + 1 == 3) ? 0 : st + 1;
    }

#pragma unroll
    for (int i = 0; i < 4; ++i) {
#pragma unroll
        for (int j = 0; j < 4; ++j) {
            const int r0 = row0 + wm + i * 16 + g;
            const int c  = col0 + wn + j * 8 + 2 * t4;
            __nv_bfloat162 p0 = __float22bfloat162_rn(make_float2(acc[i][j][0], acc[i][j][1]));
            __nv_bfloat162 p1 = __float22bfloat162_rn(make_float2(acc[i][j][2], acc[i][j][3]));
            *reinterpret_cast<__nv_bfloat162*>(&g_IinB[(size_t)r0 * H1 + c])       = p0;
            *reinterpret_cast<__nv_bfloat162*>(&g_IinB[(size_t)(r0 + 8) * H1 + c]) = p1;
        }
    }
}

// ---------------- K4: recurrent scan — 256 threads/CTA, 2 barriers/step ----------------
// Thread owns layer-1 neurons 4t..4t+3 and layer-2 neurons 2t..2t+1; tid<20 readout.
__global__ void __launch_bounds__(256) k_scan(
    const float* __restrict__ alpha1, const float* __restrict__ rho1, const float* __restrict__ beta_a1,
    const float* __restrict__ alpha2, const float* __restrict__ rho2, const float* __restrict__ beta_a2,
    const float* __restrict__ beta_out, float* __restrict__ out)
{
    __shared__ int cnt1[2], cnt2[2];
    __shared__ int act1[2][H1];
    __shared__ int act2[2][H2];

    const int b   = blockIdx.x;
    const int tid = threadIdx.x;
    const int h0  = 4 * tid;     // layer-1 base
    const int h2  = 2 * tid;     // layer-2 base

    const float4 al1 = *(const float4*)&alpha1[h0];
    const float4 r1  = *(const float4*)&rho1[h0];
    const float4 ba1 = *(const float4*)&beta_a1[h0];
    float v1[4] = {0.f, 0.f, 0.f, 0.f}, a1[4] = {0.f, 0.f, 0.f, 0.f}, s1[4] = {0.f, 0.f, 0.f, 0.f};
    const float alc1[4] = {al1.x, al1.y, al1.z, al1.w};
    const float rc1[4]  = {r1.x, r1.y, r1.z, r1.w};
    const float bac1[4] = {ba1.x, ba1.y, ba1.z, ba1.w};

    const float2 al2 = *(const float2*)&alpha2[h2];
    const float2 r2  = *(const float2*)&rho2[h2];
    const float2 ba2 = *(const float2*)&beta_a2[h2];
    float v2x = 0.f, v2y = 0.f, a2x = 0.f, a2y = 0.f, s2x = 0.f, s2y = 0.f;

    float bo = 0.f, obo = 0.f, vo = 0.f, vos = 0.f;
    if (tid < OO) { bo = beta_out[tid]; obo = 1.0f - bo; }

    if (tid == 0) { cnt1[0] = cnt1[1] = 0; cnt2[0] = cnt2[1] = 0; }
    __syncthreads();

    const uint2* Ib = reinterpret_cast<const uint2*>(g_IinB + (size_t)b * TT * H1) + tid;
    uint2 buf0 = Ib[0 * (H1 / 4)];
    uint2 buf1 = Ib[1 * (H1 / 4)];
    uint2 buf2 = Ib[2 * (H1 / 4)];
    uint2 buf3 = Ib[3 * (H1 / 4)];
    int p = 0;

    auto step = [&](uint2 packed, uint2& slot, int tn, int t) {
        float I1[4];
        {
            const __nv_bfloat162 p0 = *reinterpret_cast<const __nv_bfloat162*>(&packed.x);
            const __nv_bfloat162 p1 = *reinterpret_cast<const __nv_bfloat162*>(&packed.y);
            I1[0] = __low2float(p0); I1[1] = __high2float(p0);
            I1[2] = __low2float(p1); I1[3] = __high2float(p1);
        }
        if (tn < TT) slot = Ib[(size_t)tn * (H1 / 4)];   // prefetch 4 ahead

        const int q = p ^ 1;
        // ---- phase A: layer-1 update (reads act1[p]); reset cnt1[q]
        if (tid == 0) cnt1[q] = 0;
        const int n1 = cnt1[p];
        for (int i = 0; i < n1; ++i) {
            const float4 w = *(const float4*)&g_Wr1T[act1[p][i] * H1 + h0];
            I1[0] += w.x; I1[1] += w.y; I1[2] += w.z; I1[3] += w.w;
        }
        float ns1[4];
#pragma unroll
        for (int c = 0; c < 4; ++c) {
            v1[c] = alc1[c] * v1[c] + (1.0f - alc1[c]) * I1[c] - s1[c] - a1[c];
            ns1[c] = (v1[c] >= 1.0f) ? 1.0f : 0.0f;
            a1[c] = rc1[c] * a1[c] + bac1[c] * ns1[c];
            s1[c] = ns1[c];
        }
        __syncthreads();                                 // B1

        // ---- phase B: publish layer-1 spikes; reset cnt2[q]
        if (tid == 1) cnt2[q] = 0;
#pragma unroll
        for (int c = 0; c < 4; ++c)
            if (ns1[c] != 0.0f) { int idx = atomicAdd(&cnt1[q], 1); act1[q][idx] = h0 + c; }
        __syncthreads();                                 // B2

        // ---- phase C: layer-2 update + deferred readout of step t-1
        {
            float I2x = 0.f, I2y = 0.f;
            const int m1 = cnt1[q];
            for (int i = 0; i < m1; ++i) {
                const float2 w = *(const float2*)&g_W2T[act1[q][i] * H2 + h2];
                I2x += w.x; I2y += w.y;
            }
            const int n2 = cnt2[p];
            for (int i = 0; i < n2; ++i) {
                const float2 w = *(const float2*)&g_Wr2T[act2[p][i] * H2 + h2];
                I2x += w.x; I2y += w.y;
            }
            v2x = al2.x * v2x + (1.0f - al2.x) * I2x - s2x - a2x;
            v2y = al2.y * v2y + (1.0f - al2.y) * I2y - s2y - a2y;
            const float ns2x = (v2x >= 1.0f) ? 1.0f : 0.0f;
            const float ns2y = (v2y >= 1.0f) ? 1.0f : 0.0f;
            a2x = r2.x * a2x + ba2.x * ns2x;
            a2y = r2.y * a2y + ba2.y * ns2y;
            s2x = ns2x; s2y = ns2y;
            if (ns2x != 0.0f) { int idx = atomicAdd(&cnt2[q], 1); act2[q][idx] = h2; }
            if (ns2y != 0.0f) { int idx = atomicAdd(&cnt2[q], 1); act2[q][idx] = h2 + 1; }
        }
        if (tid < OO && t > 0) {
            float Io = 0.f;
            const int m2 = cnt2[p];
            for (int i = 0; i < m2; ++i) Io += g_WoT[act2[p][i] * OO + tid];
            vo = bo * vo + obo * Io;
            vos += vo;
        }
        p = q;
    };

    for (int t = 0; t < 248; t += 4) {
        step(buf0, buf0, t + 4, t);
        step(buf1, buf1, t + 5, t + 1);
        step(buf2, buf2, t + 6, t + 2);
        step(buf3, buf3, t + 7, t + 3);
    }
    step(buf0, buf0, TT, 248);
    step(buf1, buf1, TT, 249);

    __syncthreads();   // final act2 list complete
    if (tid < OO) {
        float Io = 0.f;
        const int m2 = cnt2[p];
        for (int i = 0; i < m2; ++i) Io += g_WoT[act2[p][i] * OO + tid];
        vo = bo * vo + obo * Io;
        vos += vo;
        out[b * OO + tid] = vos * (1.0f / (float)TT);
    }
}

// ---------------- launch ----------------
extern "C" void kernel_launch(void* const* d_in, const int* in_sizes, int n_in,
                              void* d_out, int out_size)
{
    const float* x       = (const float*)d_in[0];
    const int*   delays  = (const int*)  d_in[1];
    const float* W_in    = (const float*)d_in[2];
    const float* W_rec1  = (const float*)d_in[3];
    const float* W2      = (const float*)d_in[4];
    const float* W_rec2  = (const float*)d_in[5];
    const float* W_out   = (const float*)d_in[6];
    const float* alpha1  = (const float*)d_in[7];
    const float* rho1    = (const float*)d_in[8];
    const float* beta_a1 = (const float*)d_in[9];
    const float* alpha2  = (const float*)d_in[10];
    const float* rho2    = (const float*)d_in[11];
    const float* beta_a2 = (const float*)d_in[12];
    const float* beta_out= (const float*)d_in[13];
    float* out = (float*)d_out;

    static int smem_set = 0;
    if (!smem_set) {
        cudaFuncSetAttribute(k_gemm, cudaFuncAttributeMaxDynamicSharedMemorySize, GEMM_SMEM);
        smem_set = 1;
    }

    k_prep_build<<<PB_TOTAL, 1024>>>(x, delays, W_in, W_rec1, W2, W_rec2, W_out);

    {
        dim3 grid(H1 / BN, BT / BM);   // (8, 500)
        k_gemm<<<grid, 256, GEMM_SMEM>>>();
    }

    k_scan<<<BATCH, 256>>>(alpha1, rho1, beta_a1, alpha2, rho2, beta_a2, beta_out, out);
}

// round 8
// speedup vs baseline: 1.3127x; 1.2920x over previous
#include <cuda_runtime.h>
#include <cuda_bf16.h>
#include <stdint.h>

// ---------------- problem constants (fixed shapes) ----------------
#define BATCH 256
#define TT    250
#define CC    700
#define KP    704          // C padded (int8 bytes per row; 44*16)
#define KP16  352          // row length in uint16 units
#define H1    1024
#define H2    512
#define OO    20
#define BT    (BATCH*TT)   // 64000

// ---------------- device scratch ----------------
static __device__ uint8_t g_xd8[(size_t)BT * KP];         // delayed input {0,1} int8, 45MB
static __device__ int8_t  g_Wq[H1 * KP];                  // quantized W_in [h][c]
static __device__ float   g_qscale[H1];                   // per-row scales
static __device__ __nv_bfloat16 g_IinB[(size_t)BT * H1];  // I_in bf16 [r][h], 131MB
static __device__ float g_Wr1T[H1 * H1];                  // [j][h]
static __device__ float g_W2T[H1 * H2];                   // [j1][h2]
static __device__ float g_Wr2T[H2 * H2];                  // [j2][h2]
static __device__ float g_WoT[H2 * OO];                   // [j2][o]

// ---------------- K1: fused prep ----------------
// block ranges:
//  [0,512)      : build_xd (b = blk/2, t0 = (blk%2)*125), uint8 output
//  [512,544)    : W_in quantize, one warp per row (32 rows/block)
//  [544,1568)   : Wr1 transpose 32x32 tiles
//  [1568,2080)  : W2 transpose
//  [2080,2336)  : Wr2 transpose
//  [2336]       : WoT
#define PB_TOTAL 2337

__global__ void __launch_bounds__(1024) k_prep_build(
    const float* __restrict__ x, const int* __restrict__ delays,
    const float* __restrict__ Win, const float* __restrict__ Wr1,
    const float* __restrict__ W2, const float* __restrict__ Wr2,
    const float* __restrict__ Wo)
{
    __shared__ float stage[185][32];
    __shared__ int dsh[KP];
    __shared__ float tile[32][33];

    const int blk = blockIdx.x;
    const int tid = threadIdx.x;
    const int tx = tid & 31, ty = tid >> 5;

    if (blk < 512) {
        // ----- build_xd (uint8) -----
        const int b  = blk >> 1;
        const int t0 = (blk & 1) * 125;
        for (int i = tid; i < KP; i += 1024) dsh[i] = (i < CC) ? delays[i] : 0;

        for (int c0 = 0; c0 < KP; c0 += 32) {
            __syncthreads();
            for (int idx = tid; idx < 185 * 32; idx += 1024) {
                int r = idx >> 5;
                int c = c0 + (idx & 31);
                int tg = t0 - 60 + r;
                float v = 0.0f;
                if (tg >= 0 && tg < TT && c < CC) v = x[((size_t)b * TT + tg) * CC + c];
                stage[r][idx & 31] = v;
            }
            __syncthreads();
            const int c = c0 + tx;
            const int d = dsh[c];
            for (int tt = ty; tt < 125; tt += 32) {
                float v = (c < CC) ? stage[tt + 60 - d][tx] : 0.0f;
                g_xd8[((size_t)b * TT + t0 + tt) * KP + c] = (uint8_t)(v != 0.0f);
            }
        }
    } else if (blk < 544) {
        // ----- W_in per-row int8 quantization (warp per row) -----
        const int row = (blk - 512) * 32 + ty;
        float m = 0.0f;
        for (int c = tx; c < CC; c += 32) m = fmaxf(m, fabsf(Win[row * CC + c]));
#pragma unroll
        for (int off = 16; off; off >>= 1) m = fmaxf(m, __shfl_xor_sync(0xFFFFFFFFu, m, off));
        const float inv = (m > 0.0f) ? 127.0f / m : 0.0f;
        if (tx == 0) g_qscale[row] = m * (1.0f / 127.0f);
        for (int c = tx; c < KP; c += 32) {
            float w = (c < CC) ? Win[row * CC + c] : 0.0f;
            g_Wq[row * KP + c] = (int8_t)__float2int_rn(w * inv);
        }
    } else if (blk < 1568) {
        const int tI = blk - 544;
        const int tr = tI >> 5, tc = tI & 31;
        tile[ty][tx] = Wr1[(tr * 32 + ty) * H1 + tc * 32 + tx];
        __syncthreads();
        g_Wr1T[(tc * 32 + ty) * H1 + tr * 32 + tx] = tile[tx][ty];
    } else if (blk < 2080) {
        const int tI = blk - 1568;
        const int th = tI & 15, tj = tI >> 4;
        tile[ty][tx] = W2[(th * 32 + ty) * H1 + tj * 32 + tx];
        __syncthreads();
        g_W2T[(tj * 32 + ty) * H2 + th * 32 + tx] = tile[tx][ty];
    } else if (blk < 2336) {
        const int tI = blk - 2080;
        const int tr = tI >> 4, tc = tI & 15;
        tile[ty][tx] = Wr2[(tr * 32 + ty) * H2 + tc * 32 + tx];
        __syncthreads();
        g_Wr2T[(tc * 32 + ty) * H2 + tr * 32 + tx] = tile[tx][ty];
    } else {
        for (int i = tid; i < H2 * OO; i += 1024) {
            int j = i / OO, o = i % OO;
            g_WoT[i] = Wo[o * H2 + j];
        }
    }
}

// ---------------- K3: int8 IMMA GEMM  I_in = s_h * (xd8 @ Wq^T) ----------------
// mma.m16n8k32.s8 with ldmatrix.b16 fragments (byte-identical layouts).
// Block 128x128, K-tile = 64 int8 (32 uint16 units), 3-stage cp.async, 8 warps.
#define BM 128
#define BN 128
#define BKK 32      // uint16 units per K-tile (= 64 int8)
#define SMSTR 40    // uint16 row stride (80B): 16B aligned, ldmatrix conflict-free
#define GEMM_SMEM (3 * (BM + BN) * SMSTR * 2)   // 61440 bytes

#define CP_ASYNC16(dst_u32, src_ptr) \
    asm volatile("cp.async.cg.shared.global [%0], [%1], 16;\n" :: "r"(dst_u32), "l"(src_ptr))
#define CP_COMMIT() asm volatile("cp.async.commit_group;\n" ::)
#define CP_WAIT1()  asm volatile("cp.async.wait_group 1;\n" ::)

__global__ void __launch_bounds__(256) k_gemm()
{
    extern __shared__ uint16_t smem[];
    uint16_t* Abase = smem;
    uint16_t* Bbase = smem + 3 * BM * SMSTR;

    const int tid    = threadIdx.x;
    const int warpId = tid >> 5;
    const int lane   = tid & 31;
    const int g      = lane >> 2;
    const int t4     = lane & 3;

    const int row0 = blockIdx.y * BM;
    const int col0 = blockIdx.x * BN;
    const int wm   = (warpId & 1) * 64;
    const int wn   = (warpId >> 1) * 32;

    const int lrow0 = tid >> 2;
    const int lseg  = (tid & 3) * 8;   // uint16 units: 0,8,16,24

    const uint16_t* Ag = reinterpret_cast<const uint16_t*>(g_xd8) + (size_t)row0 * KP16;
    const uint16_t* Bg = reinterpret_cast<const uint16_t*>(g_Wq)  + (size_t)col0 * KP16;

    uint32_t sA[3], sB[3];
#pragma unroll
    for (int s = 0; s < 3; ++s) {
        sA[s] = (uint32_t)__cvta_generic_to_shared(Abase + s * BM * SMSTR);
        sB[s] = (uint32_t)__cvta_generic_to_shared(Bbase + s * BN * SMSTR);
    }

    const int aoff = ((wm + (lane & 15)) * SMSTR + (lane >> 4) * 8) * 2;
    const int boff = ((wn + (lane & 7) + ((lane >> 4) << 3)) * SMSTR + ((lane >> 3) & 1) * 8) * 2;

    int acc[4][4][4];
#pragma unroll
    for (int i = 0; i < 4; ++i)
#pragma unroll
        for (int j = 0; j < 4; ++j)
#pragma unroll
            for (int c = 0; c < 4; ++c) acc[i][j][c] = 0;

    const int NK = KP16 / BKK;   // 11

#pragma unroll
    for (int s = 0; s < 2; ++s) {
        const int k0 = s * BKK;
        CP_ASYNC16(sA[s] + (lrow0 * SMSTR + lseg) * 2,        Ag + (size_t)lrow0 * KP16 + k0 + lseg);
        CP_ASYNC16(sA[s] + ((lrow0 + 64) * SMSTR + lseg) * 2, Ag + (size_t)(lrow0 + 64) * KP16 + k0 + lseg);
        CP_ASYNC16(sB[s] + (lrow0 * SMSTR + lseg) * 2,        Bg + (size_t)lrow0 * KP16 + k0 + lseg);
        CP_ASYNC16(sB[s] + ((lrow0 + 64) * SMSTR + lseg) * 2, Bg + (size_t)(lrow0 + 64) * KP16 + k0 + lseg);
        CP_COMMIT();
    }

    int st = 0;
    for (int kt = 0; kt < NK; ++kt) {
        CP_WAIT1();
        __syncthreads();

        if (kt + 2 < NK) {
            const int s = (st + 2 >= 3) ? st - 1 : st + 2;
            const int k0 = (kt + 2) * BKK;
            CP_ASYNC16(sA[s] + (lrow0 * SMSTR + lseg) * 2,        Ag + (size_t)lrow0 * KP16 + k0 + lseg);
            CP_ASYNC16(sA[s] + ((lrow0 + 64) * SMSTR + lseg) * 2, Ag + (size_t)(lrow0 + 64) * KP16 + k0 + lseg);
            CP_ASYNC16(sB[s] + (lrow0 * SMSTR + lseg) * 2,        Bg + (size_t)lrow0 * KP16 + k0 + lseg);
            CP_ASYNC16(sB[s] + ((lrow0 + 64) * SMSTR + lseg) * 2, Bg + (size_t)(lrow0 + 64) * KP16 + k0 + lseg);
        }
        CP_COMMIT();

        const uint32_t aBase = sA[st] + aoff;
        const uint32_t bBase = sB[st] + boff;
#pragma unroll
        for (int ks = 0; ks < BKK; ks += 16) {   // 16 uint16 = 32 int8 K per step
            uint32_t af[4][4];
            uint32_t bq[2][4];
#pragma unroll
            for (int i = 0; i < 4; ++i) {
                asm volatile("ldmatrix.sync.aligned.m8n8.x4.shared.b16 {%0,%1,%2,%3}, [%4];"
                             : "=r"(af[i][0]), "=r"(af[i][1]), "=r"(af[i][2]), "=r"(af[i][3])
                             : "r"(aBase + (i * 16 * SMSTR + ks) * 2));
            }
#pragma unroll
            for (int j2 = 0; j2 < 2; ++j2) {
                asm volatile("ldmatrix.sync.aligned.m8n8.x4.shared.b16 {%0,%1,%2,%3}, [%4];"
                             : "=r"(bq[j2][0]), "=r"(bq[j2][1]), "=r"(bq[j2][2]), "=r"(bq[j2][3])
                             : "r"(bBase + (j2 * 16 * SMSTR + ks) * 2));
            }
#pragma unroll
            for (int i = 0; i < 4; ++i)
#pragma unroll
                for (int j = 0; j < 4; ++j) {
                    const uint32_t b0 = bq[j >> 1][(j & 1) * 2];
                    const uint32_t b1 = bq[j >> 1][(j & 1) * 2 + 1];
                    asm volatile(
                        "mma.sync.aligned.m16n8k32.row.col.s32.s8.s8.s32 "
                        "{%0,%1,%2,%3}, {%4,%5,%6,%7}, {%8,%9}, {%0,%1,%2,%3};\n"
                        : "+r"(acc[i][j][0]), "+r"(acc[i][j][1]),
                          "+r"(acc[i][j][2]), "+r"(acc[i][j][3])
                        : "r"(af[i][0]), "r"(af[i][1]), "r"(af[i][2]), "r"(af[i][3]),
                          "r"(b0), "r"(b1));
                }
        }
        st = (st + 1 == 3) ? 0 : st + 1;
    }

    // epilogue: dequantize with per-column scale, write bf16
#pragma unroll
    for (int j = 0; j < 4; ++j) {
        const int c = col0 + wn + j * 8 + 2 * t4;
        const float sc0 = g_qscale[c];
        const float sc1 = g_qscale[c + 1];
#pragma unroll
        for (int i = 0; i < 4; ++i) {
            const int r0 = row0 + wm + i * 16 + g;
            __nv_bfloat162 p0 = __float22bfloat162_rn(
                make_float2(sc0 * (float)acc[i][j][0], sc1 * (float)acc[i][j][1]));
            __nv_bfloat162 p1 = __float22bfloat162_rn(
                make_float2(sc0 * (float)acc[i][j][2], sc1 * (float)acc[i][j][3]));
            *reinterpret_cast<__nv_bfloat162*>(&g_IinB[(size_t)r0 * H1 + c])       = p0;
            *reinterpret_cast<__nv_bfloat162*>(&g_IinB[(size_t)(r0 + 8) * H1 + c]) = p1;
        }
    }
}

// ---------------- K4: recurrent scan — 256 threads/CTA, 2 barriers/step ----------------
__global__ void __launch_bounds__(256) k_scan(
    const float* __restrict__ alpha1, const float* __restrict__ rho1, const float* __restrict__ beta_a1,
    const float* __restrict__ alpha2, const float* __restrict__ rho2, const float* __restrict__ beta_a2,
    const float* __restrict__ beta_out, float* __restrict__ out)
{
    __shared__ int cnt1[2], cnt2[2];
    __shared__ int act1[2][H1];
    __shared__ int act2[2][H2];

    const int b   = blockIdx.x;
    const int tid = threadIdx.x;
    const int h0  = 4 * tid;
    const int h2  = 2 * tid;

    const float4 al1 = *(const float4*)&alpha1[h0];
    const float4 r1  = *(const float4*)&rho1[h0];
    const float4 ba1 = *(const float4*)&beta_a1[h0];
    float v1[4] = {0.f, 0.f, 0.f, 0.f}, a1[4] = {0.f, 0.f, 0.f, 0.f}, s1[4] = {0.f, 0.f, 0.f, 0.f};
    const float alc1[4] = {al1.x, al1.y, al1.z, al1.w};
    const float rc1[4]  = {r1.x, r1.y, r1.z, r1.w};
    const float bac1[4] = {ba1.x, ba1.y, ba1.z, ba1.w};

    const float2 al2 = *(const float2*)&alpha2[h2];
    const float2 r2  = *(const float2*)&rho2[h2];
    const float2 ba2 = *(const float2*)&beta_a2[h2];
    float v2x = 0.f, v2y = 0.f, a2x = 0.f, a2y = 0.f, s2x = 0.f, s2y = 0.f;

    float bo = 0.f, obo = 0.f, vo = 0.f, vos = 0.f;
    if (tid < OO) { bo = beta_out[tid]; obo = 1.0f - bo; }

    if (tid == 0) { cnt1[0] = cnt1[1] = 0; cnt2[0] = cnt2[1] = 0; }
    __syncthreads();

    const uint2* Ib = reinterpret_cast<const uint2*>(g_IinB + (size_t)b * TT * H1) + tid;
    uint2 buf0 = Ib[0 * (H1 / 4)];
    uint2 buf1 = Ib[1 * (H1 / 4)];
    uint2 buf2 = Ib[2 * (H1 / 4)];
    uint2 buf3 = Ib[3 * (H1 / 4)];
    int p = 0;

    auto step = [&](uint2 packed, uint2& slot, int tn, int t) {
        float I1[4];
        {
            const __nv_bfloat162 p0 = *reinterpret_cast<const __nv_bfloat162*>(&packed.x);
            const __nv_bfloat162 p1 = *reinterpret_cast<const __nv_bfloat162*>(&packed.y);
            I1[0] = __low2float(p0); I1[1] = __high2float(p0);
            I1[2] = __low2float(p1); I1[3] = __high2float(p1);
        }
        if (tn < TT) slot = Ib[(size_t)tn * (H1 / 4)];

        const int q = p ^ 1;
        if (tid == 0) cnt1[q] = 0;
        const int n1 = cnt1[p];
        for (int i = 0; i < n1; ++i) {
            const float4 w = *(const float4*)&g_Wr1T[act1[p][i] * H1 + h0];
            I1[0] += w.x; I1[1] += w.y; I1[2] += w.z; I1[3] += w.w;
        }
        float ns1[4];
#pragma unroll
        for (int c = 0; c < 4; ++c) {
            v1[c] = alc1[c] * v1[c] + (1.0f - alc1[c]) * I1[c] - s1[c] - a1[c];
            ns1[c] = (v1[c] >= 1.0f) ? 1.0f : 0.0f;
            a1[c] = rc1[c] * a1[c] + bac1[c] * ns1[c];
            s1[c] = ns1[c];
        }
        __syncthreads();                                 // B1

        if (tid == 1) cnt2[q] = 0;
#pragma unroll
        for (int c = 0; c < 4; ++c)
            if (ns1[c] != 0.0f) { int idx = atomicAdd(&cnt1[q], 1); act1[q][idx] = h0 + c; }
        __syncthreads();                                 // B2

        {
            float I2x = 0.f, I2y = 0.f;
            const int m1 = cnt1[q];
            for (int i = 0; i < m1; ++i) {
                const float2 w = *(const float2*)&g_W2T[act1[q][i] * H2 + h2];
                I2x += w.x; I2y += w.y;
            }
            const int n2 = cnt2[p];
            for (int i = 0; i < n2; ++i) {
                const float2 w = *(const float2*)&g_Wr2T[act2[p][i] * H2 + h2];
                I2x += w.x; I2y += w.y;
            }
            v2x = al2.x * v2x + (1.0f - al2.x) * I2x - s2x - a2x;
            v2y = al2.y * v2y + (1.0f - al2.y) * I2y - s2y - a2y;
            const float ns2x = (v2x >= 1.0f) ? 1.0f : 0.0f;
            const float ns2y = (v2y >= 1.0f) ? 1.0f : 0.0f;
            a2x = r2.x * a2x + ba2.x * ns2x;
            a2y = r2.y * a2y + ba2.y * ns2y;
            s2x = ns2x; s2y = ns2y;
            if (ns2x != 0.0f) { int idx = atomicAdd(&cnt2[q], 1); act2[q][idx] = h2; }
            if (ns2y != 0.0f) { int idx = atomicAdd(&cnt2[q], 1); act2[q][idx] = h2 + 1; }
        }
        if (tid < OO && t > 0) {
            float Io = 0.f;
            const int m2 = cnt2[p];
            for (int i = 0; i < m2; ++i) Io += g_WoT[act2[p][i] * OO + tid];
            vo = bo * vo + obo * Io;
            vos += vo;
        }
        p = q;
    };

    for (int t = 0; t < 248; t += 4) {
        step(buf0, buf0, t + 4, t);
        step(buf1, buf1, t + 5, t + 1);
        step(buf2, buf2, t + 6, t + 2);
        step(buf3, buf3, t + 7, t + 3);
    }
    step(buf0, buf0, TT, 248);
    step(buf1, buf1, TT, 249);

    __syncthreads();
    if (tid < OO) {
        float Io = 0.f;
        const int m2 = cnt2[p];
        for (int i = 0; i < m2; ++i) Io += g_WoT[act2[p][i] * OO + tid];
        vo = bo * vo + obo * Io;
        vos += vo;
        out[b * OO + tid] = vos * (1.0f / (float)TT);
    }
}

// ---------------- launch ----------------
extern "C" void kernel_launch(void* const* d_in, const int* in_sizes, int n_in,
                              void* d_out, int out_size)
{
    const float* x       = (const float*)d_in[0];
    const int*   delays  = (const int*)  d_in[1];
    const float* W_in    = (const float*)d_in[2];
    const float* W_rec1  = (const float*)d_in[3];
    const float* W2      = (const float*)d_in[4];
    const float* W_rec2  = (const float*)d_in[5];
    const float* W_out   = (const float*)d_in[6];
    const float* alpha1  = (const float*)d_in[7];
    const float* rho1    = (const float*)d_in[8];
    const float* beta_a1 = (const float*)d_in[9];
    const float* alpha2  = (const float*)d_in[10];
    const float* rho2    = (const float*)d_in[11];
    const float* beta_a2 = (const float*)d_in[12];
    const float* beta_out= (const float*)d_in[13];
    float* out = (float*)d_out;

    static int smem_set = 0;
    if (!smem_set) {
        cudaFuncSetAttribute(k_gemm, cudaFuncAttributeMaxDynamicSharedMemorySize, GEMM_SMEM);
        smem_set = 1;
    }

    k_prep_build<<<PB_TOTAL, 1024>>>(x, delays, W_in, W_rec1, W2, W_rec2, W_out);

    {
        dim3 grid(H1 / BN, BT / BM);   // (8, 500)
        k_gemm<<<grid, 256, GEMM_SMEM>>>();
    }

    k_scan<<<BATCH, 256>>>(alpha1, rho1, beta_a1, alpha2, rho2, beta_a2, beta_out, out);
}

// round 9
// speedup vs baseline: 1.8524x; 1.4111x over previous
#include <cuda_runtime.h>
#include <cuda_bf16.h>
#include <stdint.h>

// ---------------- problem constants (fixed shapes) ----------------
#define BATCH 256
#define TT    250
#define CC    700
#define KP    704          // C padded (int8 bytes per row; 44*16)
#define KP16  352          // row length in uint16 units
#define H1    1024
#define H2    512
#define OO    20
#define BT    (BATCH*TT)   // 64000

// ---------------- device scratch ----------------
static __device__ uint8_t g_xd8[(size_t)BT * KP];         // delayed input {0,1} int8, 45MB
static __device__ int8_t  g_Wq[H1 * KP];                  // quantized W_in [h][c]
static __device__ float   g_qscale[H1];                   // per-row scales
static __device__ __nv_bfloat16 g_IinB[(size_t)BT * H1];  // I_in bf16 [r][h], 131MB
static __device__ float g_Wr1T[H1 * H1];                  // [j][h]
static __device__ float g_W2T[H1 * H2];                   // [j1][h2]
static __device__ float g_Wr2T[H2 * H2];                  // [j2][h2]
static __device__ float g_WoT[H2 * OO];                   // [j2][o]

// ---------------- K1: fused prep ----------------
// block ranges:
//  [0,256)      : build_xd, one block per batch, x read ONCE
//  [256,288)    : W_in quantize, one warp per row (32 rows/block)
//  [288,1312)   : Wr1 transpose 32x32 tiles
//  [1312,1824)  : W2 transpose
//  [1824,2080)  : Wr2 transpose
//  [2080]       : WoT
#define PB_TOTAL 2081

__global__ void __launch_bounds__(1024) k_prep_build(
    const float* __restrict__ x, const int* __restrict__ delays,
    const float* __restrict__ Win, const float* __restrict__ Wr1,
    const float* __restrict__ W2, const float* __restrict__ Wr2,
    const float* __restrict__ Wo)
{
    __shared__ uint8_t stage8[TT * 128];   // 32000 B: full T for a 128-channel tile
    __shared__ int dsh[KP];
    __shared__ float tile[32][33];

    const int blk = blockIdx.x;
    const int tid = threadIdx.x;
    const int tx = tid & 31, ty = tid >> 5;

    if (blk < 256) {
        // ----- build_xd: one batch, 6 channel tiles of 128 -----
        const int b = blk;
        for (int i = tid; i < KP; i += 1024) dsh[i] = (i < CC) ? delays[i] : 0;

        const float* xb = x + (size_t)b * TT * CC;
        uint32_t* outw = reinterpret_cast<uint32_t*>(g_xd8) + (size_t)b * TT * (KP / 4);

        for (int c0 = 0; c0 < KP; c0 += 128) {
            const int w = (c0 + 128 <= CC) ? 128 : (CC > c0 ? CC - c0 : 0);
            __syncthreads();
            // phase 1: read x rows coalesced, store 0/1 bytes
            for (int idx = tid; idx < TT * 128; idx += 1024) {
                const int t = idx >> 7, c = idx & 127;
                uint8_t v = 0;
                if (c < w) v = (uint8_t)(xb[(size_t)t * CC + c0 + c] != 0.0f);
                stage8[t * 128 + c] = v;
            }
            __syncthreads();
            // phase 2: apply per-channel delay, pack 4 bytes/thread, coalesced write
            for (int idx = tid; idx < TT * 32; idx += 1024) {
                const int t = idx >> 5, w4 = idx & 31;
                uint32_t word = 0;
#pragma unroll
                for (int j = 0; j < 4; ++j) {
                    const int c = c0 + w4 * 4 + j;
                    const int ttt = t - dsh[c];
                    uint8_t byte = 0;
                    if (ttt >= 0 && (w4 * 4 + j) < w) byte = stage8[ttt * 128 + w4 * 4 + j];
                    word |= (uint32_t)byte << (8 * j);
                }
                outw[(size_t)t * (KP / 4) + (c0 >> 2) + w4] = word;
            }
        }
    } else if (blk < 288) {
        // ----- W_in per-row int8 quantization (warp per row) -----
        const int row = (blk - 256) * 32 + ty;
        float m = 0.0f;
        for (int c = tx; c < CC; c += 32) m = fmaxf(m, fabsf(Win[row * CC + c]));
#pragma unroll
        for (int off = 16; off; off >>= 1) m = fmaxf(m, __shfl_xor_sync(0xFFFFFFFFu, m, off));
        const float inv = (m > 0.0f) ? 127.0f / m : 0.0f;
        if (tx == 0) g_qscale[row] = m * (1.0f / 127.0f);
        for (int c = tx; c < KP; c += 32) {
            float wv = (c < CC) ? Win[row * CC + c] : 0.0f;
            g_Wq[row * KP + c] = (int8_t)__float2int_rn(wv * inv);
        }
    } else if (blk < 1312) {
        const int tI = blk - 288;
        const int tr = tI >> 5, tc = tI & 31;
        tile[ty][tx] = Wr1[(tr * 32 + ty) * H1 + tc * 32 + tx];
        __syncthreads();
        g_Wr1T[(tc * 32 + ty) * H1 + tr * 32 + tx] = tile[tx][ty];
    } else if (blk < 1824) {
        const int tI = blk - 1312;
        const int th = tI & 15, tj = tI >> 4;
        tile[ty][tx] = W2[(th * 32 + ty) * H1 + tj * 32 + tx];
        __syncthreads();
        g_W2T[(tj * 32 + ty) * H2 + th * 32 + tx] = tile[tx][ty];
    } else if (blk < 2080) {
        const int tI = blk - 1824;
        const int tr = tI >> 4, tc = tI & 15;
        tile[ty][tx] = Wr2[(tr * 32 + ty) * H2 + tc * 32 + tx];
        __syncthreads();
        g_Wr2T[(tc * 32 + ty) * H2 + tr * 32 + tx] = tile[tx][ty];
    } else {
        for (int i = tid; i < H2 * OO; i += 1024) {
            int j = i / OO, o = i % OO;
            g_WoT[i] = Wo[o * H2 + j];
        }
    }
}

// ---------------- K3: int8 IMMA GEMM, 4-stage cp.async ----------------
#define BM 128
#define BN 128
#define BKK 32      // uint16 units per K-tile (= 64 int8)
#define SMSTR 40    // uint16 row stride (80B)
#define NSTG 4
#define GEMM_SMEM (NSTG * (BM + BN) * SMSTR * 2)   // 81920 bytes

#define CP_ASYNC16(dst_u32, src_ptr) \
    asm volatile("cp.async.cg.shared.global [%0], [%1], 16;\n" :: "r"(dst_u32), "l"(src_ptr))
#define CP_COMMIT() asm volatile("cp.async.commit_group;\n" ::)
#define CP_WAIT2()  asm volatile("cp.async.wait_group 2;\n" ::)

__global__ void __launch_bounds__(256, 2) k_gemm()
{
    extern __shared__ uint16_t smem[];
    uint16_t* Abase = smem;
    uint16_t* Bbase = smem + NSTG * BM * SMSTR;

    const int tid    = threadIdx.x;
    const int warpId = tid >> 5;
    const int lane   = tid & 31;
    const int g      = lane >> 2;
    const int t4     = lane & 3;

    const int row0 = blockIdx.y * BM;
    const int col0 = blockIdx.x * BN;
    const int wm   = (warpId & 1) * 64;
    const int wn   = (warpId >> 1) * 32;

    const int lrow0 = tid >> 2;
    const int lseg  = (tid & 3) * 8;   // uint16 units

    const uint16_t* Ag = reinterpret_cast<const uint16_t*>(g_xd8) + (size_t)row0 * KP16;
    const uint16_t* Bg = reinterpret_cast<const uint16_t*>(g_Wq)  + (size_t)col0 * KP16;

    uint32_t sA[NSTG], sB[NSTG];
#pragma unroll
    for (int s = 0; s < NSTG; ++s) {
        sA[s] = (uint32_t)__cvta_generic_to_shared(Abase + s * BM * SMSTR);
        sB[s] = (uint32_t)__cvta_generic_to_shared(Bbase + s * BN * SMSTR);
    }

    const int aoff = ((wm + (lane & 15)) * SMSTR + (lane >> 4) * 8) * 2;
    const int boff = ((wn + (lane & 7) + ((lane >> 4) << 3)) * SMSTR + ((lane >> 3) & 1) * 8) * 2;

    int acc[4][4][4];
#pragma unroll
    for (int i = 0; i < 4; ++i)
#pragma unroll
        for (int j = 0; j < 4; ++j)
#pragma unroll
            for (int c = 0; c < 4; ++c) acc[i][j][c] = 0;

    const int NK = KP16 / BKK;   // 11

#pragma unroll
    for (int s = 0; s < 3; ++s) {
        const int k0 = s * BKK;
        CP_ASYNC16(sA[s] + (lrow0 * SMSTR + lseg) * 2,        Ag + (size_t)lrow0 * KP16 + k0 + lseg);
        CP_ASYNC16(sA[s] + ((lrow0 + 64) * SMSTR + lseg) * 2, Ag + (size_t)(lrow0 + 64) * KP16 + k0 + lseg);
        CP_ASYNC16(sB[s] + (lrow0 * SMSTR + lseg) * 2,        Bg + (size_t)lrow0 * KP16 + k0 + lseg);
        CP_ASYNC16(sB[s] + ((lrow0 + 64) * SMSTR + lseg) * 2, Bg + (size_t)(lrow0 + 64) * KP16 + k0 + lseg);
        CP_COMMIT();
    }

    for (int kt = 0; kt < NK; ++kt) {
        const int st = kt & 3;
        CP_WAIT2();
        __syncthreads();

        if (kt + 3 < NK) {
            const int s = (kt + 3) & 3;
            const int k0 = (kt + 3) * BKK;
            CP_ASYNC16(sA[s] + (lrow0 * SMSTR + lseg) * 2,        Ag + (size_t)lrow0 * KP16 + k0 + lseg);
            CP_ASYNC16(sA[s] + ((lrow0 + 64) * SMSTR + lseg) * 2, Ag + (size_t)(lrow0 + 64) * KP16 + k0 + lseg);
            CP_ASYNC16(sB[s] + (lrow0 * SMSTR + lseg) * 2,        Bg + (size_t)lrow0 * KP16 + k0 + lseg);
            CP_ASYNC16(sB[s] + ((lrow0 + 64) * SMSTR + lseg) * 2, Bg + (size_t)(lrow0 + 64) * KP16 + k0 + lseg);
        }
        CP_COMMIT();

        const uint32_t aBase = sA[st] + aoff;
        const uint32_t bBase = sB[st] + boff;
#pragma unroll
        for (int ks = 0; ks < BKK; ks += 16) {
            uint32_t af[4][4];
            uint32_t bq[2][4];
#pragma unroll
            for (int i = 0; i < 4; ++i) {
                asm volatile("ldmatrix.sync.aligned.m8n8.x4.shared.b16 {%0,%1,%2,%3}, [%4];"
                             : "=r"(af[i][0]), "=r"(af[i][1]), "=r"(af[i][2]), "=r"(af[i][3])
                             : "r"(aBase + (i * 16 * SMSTR + ks) * 2));
            }
#pragma unroll
            for (int j2 = 0; j2 < 2; ++j2) {
                asm volatile("ldmatrix.sync.aligned.m8n8.x4.shared.b16 {%0,%1,%2,%3}, [%4];"
                             : "=r"(bq[j2][0]), "=r"(bq[j2][1]), "=r"(bq[j2][2]), "=r"(bq[j2][3])
                             : "r"(bBase + (j2 * 16 * SMSTR + ks) * 2));
            }
#pragma unroll
            for (int i = 0; i < 4; ++i)
#pragma unroll
                for (int j = 0; j < 4; ++j) {
                    const uint32_t b0 = bq[j >> 1][(j & 1) * 2];
                    const uint32_t b1 = bq[j >> 1][(j & 1) * 2 + 1];
                    asm volatile(
                        "mma.sync.aligned.m16n8k32.row.col.s32.s8.s8.s32 "
                        "{%0,%1,%2,%3}, {%4,%5,%6,%7}, {%8,%9}, {%0,%1,%2,%3};\n"
                        : "+r"(acc[i][j][0]), "+r"(acc[i][j][1]),
                          "+r"(acc[i][j][2]), "+r"(acc[i][j][3])
                        : "r"(af[i][0]), "r"(af[i][1]), "r"(af[i][2]), "r"(af[i][3]),
                          "r"(b0), "r"(b1));
                }
        }
    }

    // epilogue: dequantize with per-column scale, write bf16
#pragma unroll
    for (int j = 0; j < 4; ++j) {
        const int c = col0 + wn + j * 8 + 2 * t4;
        const float sc0 = g_qscale[c];
        const float sc1 = g_qscale[c + 1];
#pragma unroll
        for (int i = 0; i < 4; ++i) {
            const int r0 = row0 + wm + i * 16 + g;
            __nv_bfloat162 p0 = __float22bfloat162_rn(
                make_float2(sc0 * (float)acc[i][j][0], sc1 * (float)acc[i][j][1]));
            __nv_bfloat162 p1 = __float22bfloat162_rn(
                make_float2(sc0 * (float)acc[i][j][2], sc1 * (float)acc[i][j][3]));
            *reinterpret_cast<__nv_bfloat162*>(&g_IinB[(size_t)r0 * H1 + c])       = p0;
            *reinterpret_cast<__nv_bfloat162*>(&g_IinB[(size_t)(r0 + 8) * H1 + c]) = p1;
        }
    }
}

// ---------------- K4: recurrent scan — 128 threads/CTA, 2 barriers/step ----------------
// Thread owns L1 neurons 8t..8t+7 and L2 neurons 4t..4t+3; tid<20 readout.
__global__ void __launch_bounds__(128) k_scan(
    const float* __restrict__ alpha1, const float* __restrict__ rho1, const float* __restrict__ beta_a1,
    const float* __restrict__ alpha2, const float* __restrict__ rho2, const float* __restrict__ beta_a2,
    const float* __restrict__ beta_out, float* __restrict__ out)
{
    __shared__ int cnt1[2], cnt2[2];
    __shared__ int act1[2][H1];
    __shared__ int act2[2][H2];

    const int b   = blockIdx.x;
    const int tid = threadIdx.x;
    const int h0  = 8 * tid;
    const int h2  = 4 * tid;

    float alc1[8], rc1[8], bac1[8], v1[8], a1[8], s1[8];
#pragma unroll
    for (int k = 0; k < 2; ++k) {
        const float4 a = *(const float4*)&alpha1[h0 + 4 * k];
        const float4 r = *(const float4*)&rho1[h0 + 4 * k];
        const float4 bb = *(const float4*)&beta_a1[h0 + 4 * k];
        alc1[4*k] = a.x; alc1[4*k+1] = a.y; alc1[4*k+2] = a.z; alc1[4*k+3] = a.w;
        rc1[4*k] = r.x; rc1[4*k+1] = r.y; rc1[4*k+2] = r.z; rc1[4*k+3] = r.w;
        bac1[4*k] = bb.x; bac1[4*k+1] = bb.y; bac1[4*k+2] = bb.z; bac1[4*k+3] = bb.w;
    }
#pragma unroll
    for (int c = 0; c < 8; ++c) { v1[c] = 0.f; a1[c] = 0.f; s1[c] = 0.f; }

    float alc2[4], rc2[4], bac2[4], v2[4], a2[4], s2[4];
    {
        const float4 a = *(const float4*)&alpha2[h2];
        const float4 r = *(const float4*)&rho2[h2];
        const float4 bb = *(const float4*)&beta_a2[h2];
        alc2[0] = a.x; alc2[1] = a.y; alc2[2] = a.z; alc2[3] = a.w;
        rc2[0] = r.x; rc2[1] = r.y; rc2[2] = r.z; rc2[3] = r.w;
        bac2[0] = bb.x; bac2[1] = bb.y; bac2[2] = bb.z; bac2[3] = bb.w;
    }
#pragma unroll
    for (int c = 0; c < 4; ++c) { v2[c] = 0.f; a2[c] = 0.f; s2[c] = 0.f; }

    float bo = 0.f, obo = 0.f, vo = 0.f, vos = 0.f;
    if (tid < OO) { bo = beta_out[tid]; obo = 1.0f - bo; }

    if (tid == 0) { cnt1[0] = cnt1[1] = 0; cnt2[0] = cnt2[1] = 0; }
    __syncthreads();

    const uint4* Ib = reinterpret_cast<const uint4*>(g_IinB + (size_t)b * TT * H1) + tid;
    uint4 buf0 = Ib[0 * (H1 / 8)];
    uint4 buf1 = Ib[1 * (H1 / 8)];
    uint4 buf2 = Ib[2 * (H1 / 8)];
    uint4 buf3 = Ib[3 * (H1 / 8)];
    int p = 0;

    auto step = [&](uint4 packed, uint4& slot, int tn, int t) {
        float I1[8];
        {
            const uint32_t pw[4] = {packed.x, packed.y, packed.z, packed.w};
#pragma unroll
            for (int k = 0; k < 4; ++k) {
                const __nv_bfloat162 bp = *reinterpret_cast<const __nv_bfloat162*>(&pw[k]);
                I1[2*k]   = __low2float(bp);
                I1[2*k+1] = __high2float(bp);
            }
        }
        if (tn < TT) slot = Ib[(size_t)tn * (H1 / 8)];   // prefetch 4 ahead

        const int q = p ^ 1;
        // ---- phase A: layer-1 update (reads act1[p]); reset cnt1[q]
        if (tid == 0) cnt1[q] = 0;
        const int n1 = cnt1[p];
        for (int i = 0; i < n1; ++i) {
            const float* wr = &g_Wr1T[act1[p][i] * H1 + h0];
            const float4 w0 = *(const float4*)wr;
            const float4 w1 = *(const float4*)(wr + 4);
            I1[0] += w0.x; I1[1] += w0.y; I1[2] += w0.z; I1[3] += w0.w;
            I1[4] += w1.x; I1[5] += w1.y; I1[6] += w1.z; I1[7] += w1.w;
        }
        float ns1[8];
#pragma unroll
        for (int c = 0; c < 8; ++c) {
            v1[c] = alc1[c] * v1[c] + (1.0f - alc1[c]) * I1[c] - s1[c] - a1[c];
            ns1[c] = (v1[c] >= 1.0f) ? 1.0f : 0.0f;
            a1[c] = rc1[c] * a1[c] + bac1[c] * ns1[c];
            s1[c] = ns1[c];
        }
        __syncthreads();                                 // B1

        // ---- phase B: publish layer-1 spikes; reset cnt2[q]
        if (tid == 1) cnt2[q] = 0;
#pragma unroll
        for (int c = 0; c < 8; ++c)
            if (ns1[c] != 0.0f) { int idx = atomicAdd(&cnt1[q], 1); act1[q][idx] = h0 + c; }
        __syncthreads();                                 // B2

        // ---- phase C: layer-2 update + deferred readout of step t-1
        {
            float I2[4] = {0.f, 0.f, 0.f, 0.f};
            const int m1 = cnt1[q];
            for (int i = 0; i < m1; ++i) {
                const float4 w = *(const float4*)&g_W2T[act1[q][i] * H2 + h2];
                I2[0] += w.x; I2[1] += w.y; I2[2] += w.z; I2[3] += w.w;
            }
            const int n2 = cnt2[p];
            for (int i = 0; i < n2; ++i) {
                const float4 w = *(const float4*)&g_Wr2T[act2[p][i] * H2 + h2];
                I2[0] += w.x; I2[1] += w.y; I2[2] += w.z; I2[3] += w.w;
            }
            float ns2[4];
#pragma unroll
            for (int c = 0; c < 4; ++c) {
                v2[c] = alc2[c] * v2[c] + (1.0f - alc2[c]) * I2[c] - s2[c] - a2[c];
                ns2[c] = (v2[c] >= 1.0f) ? 1.0f : 0.0f;
                a2[c] = rc2[c] * a2[c] + bac2[c] * ns2[c];
                s2[c] = ns2[c];
            }
#pragma unroll
            for (int c = 0; c < 4; ++c)
                if (ns2[c] != 0.0f) { int idx = atomicAdd(&cnt2[q], 1); act2[q][idx] = h2 + c; }
        }
        if (tid < OO && t > 0) {
            float Io = 0.f;
            const int m2 = cnt2[p];
            for (int i = 0; i < m2; ++i) Io += g_WoT[act2[p][i] * OO + tid];
            vo = bo * vo + obo * Io;
            vos += vo;
        }
        p = q;
    };

    for (int t = 0; t < 248; t += 4) {
        step(buf0, buf0, t + 4, t);
        step(buf1, buf1, t + 5, t + 1);
        step(buf2, buf2, t + 6, t + 2);
        step(buf3, buf3, t + 7, t + 3);
    }
    step(buf0, buf0, TT, 248);
    step(buf1, buf1, TT, 249);

    __syncthreads();
    if (tid < OO) {
        float Io = 0.f;
        const int m2 = cnt2[p];
        for (int i = 0; i < m2; ++i) Io += g_WoT[act2[p][i] * OO + tid];
        vo = bo * vo + obo * Io;
        vos += vo;
        out[b * OO + tid] = vos * (1.0f / (float)TT);
    }
}

// ---------------- launch ----------------
extern "C" void kernel_launch(void* const* d_in, const int* in_sizes, int n_in,
                              void* d_out, int out_size)
{
    const float* x       = (const float*)d_in[0];
    const int*   delays  = (const int*)  d_in[1];
    const float* W_in    = (const float*)d_in[2];
    const float* W_rec1  = (const float*)d_in[3];
    const float* W2      = (const float*)d_in[4];
    const float* W_rec2  = (const float*)d_in[5];
    const float* W_out   = (const float*)d_in[6];
    const float* alpha1  = (const float*)d_in[7];
    const float* rho1    = (const float*)d_in[8];
    const float* beta_a1 = (const float*)d_in[9];
    const float* alpha2  = (const float*)d_in[10];
    const float* rho2    = (const float*)d_in[11];
    const float* beta_a2 = (const float*)d_in[12];
    const float* beta_out= (const float*)d_in[13];
    float* out = (float*)d_out;

    static int smem_set = 0;
    if (!smem_set) {
        cudaFuncSetAttribute(k_gemm, cudaFuncAttributeMaxDynamicSharedMemorySize, GEMM_SMEM);
        smem_set = 1;
    }

    k_prep_build<<<PB_TOTAL, 1024>>>(x, delays, W_in, W_rec1, W2, W_rec2, W_out);

    {
        dim3 grid(H1 / BN, BT / BM);   // (8, 500)
        k_gemm<<<grid, 256, GEMM_SMEM>>>();
    }

    k_scan<<<BATCH, 128>>>(alpha1, rho1, beta_a1, alpha2, rho2, beta_a2, beta_out, out);
}

// round 10
// speedup vs baseline: 1.9148x; 1.0337x over previous
#include <cuda_runtime.h>
#include <cuda_bf16.h>
#include <stdint.h>

// ---------------- problem constants (fixed shapes) ----------------
#define BATCH 256
#define TT    250
#define CC    700
#define KP    704          // C padded (int8 bytes per row; 44*16)
#define KP16  352          // row length in uint16 units
#define H1    1024
#define H2    512
#define OO    20
#define BT    (BATCH*TT)   // 64000

// ---------------- device scratch ----------------
static __device__ uint8_t g_xd8[(size_t)BT * KP];         // delayed input {0,1} int8, 45MB
static __device__ int8_t  g_Wq[H1 * KP];                  // quantized W_in [h][c]
static __device__ float   g_qscale[H1];                   // per-row scales
static __device__ __nv_bfloat16 g_IinB[(size_t)BT * H1];  // I_in bf16 [r][h], 131MB
static __device__ float g_Wr1T[H1 * H1];                  // [j][h]
static __device__ float g_W2T[H1 * H2];                   // [j1][h2]
static __device__ float g_Wr2T[H2 * H2];                  // [j2][h2]
static __device__ float g_WoT[H2 * OO];                   // [j2][o]

#define CP_ASYNC16(dst_u32, src_ptr) \
    asm volatile("cp.async.cg.shared.global [%0], [%1], 16;\n" :: "r"(dst_u32), "l"(src_ptr))
#define CP_COMMIT() asm volatile("cp.async.commit_group;\n" ::)

// ---------------- K1: fused prep ----------------
// block ranges:
//  [0,256)      : build_xd, one block per batch, x read ONCE (float4)
//  [256,288)    : W_in quantize, one warp per row (32 rows/block)
//  [288,1312)   : Wr1 transpose 32x32 tiles
//  [1312,1824)  : W2 transpose
//  [1824,2080)  : Wr2 transpose
//  [2080]       : WoT
#define PB_TOTAL 2081

__global__ void __launch_bounds__(1024) k_prep_build(
    const float* __restrict__ x, const int* __restrict__ delays,
    const float* __restrict__ Win, const float* __restrict__ Wr1,
    const float* __restrict__ W2, const float* __restrict__ Wr2,
    const float* __restrict__ Wo)
{
    __shared__ uint8_t stage8[TT * 128];   // 32000 B: full T for a 128-channel tile
    __shared__ int dsh[KP];
    __shared__ float tile[32][33];

    const int blk = blockIdx.x;
    const int tid = threadIdx.x;
    const int tx = tid & 31, ty = tid >> 5;

    if (blk < 256) {
        // ----- build_xd: one batch, 6 channel tiles of 128 -----
        const int b = blk;
        for (int i = tid; i < KP; i += 1024) dsh[i] = (i < CC) ? delays[i] : 0;

        const float* xb = x + (size_t)b * TT * CC;
        uint32_t* outw = reinterpret_cast<uint32_t*>(g_xd8) + (size_t)b * TT * (KP / 4);

        for (int c0 = 0; c0 < KP; c0 += 128) {
            const int w = (c0 + 128 <= CC) ? 128 : (CC > c0 ? CC - c0 : 0);   // 128 or 60; div by 4
            __syncthreads();
            // phase 1: float4 reads of x, packed 0/1-byte uint32 stores to stage
            for (int idx = tid; idx < TT * 32; idx += 1024) {
                const int t = idx >> 5, c4 = idx & 31;
                uint32_t word = 0;
                if (c4 * 4 < w) {
                    const float4 v = *(const float4*)&xb[(size_t)t * CC + c0 + c4 * 4];
                    word  = (uint32_t)(v.x != 0.0f);
                    word |= (uint32_t)(v.y != 0.0f) << 8;
                    word |= (uint32_t)(v.z != 0.0f) << 16;
                    word |= (uint32_t)(v.w != 0.0f) << 24;
                }
                *reinterpret_cast<uint32_t*>(&stage8[t * 128 + c4 * 4]) = word;
            }
            __syncthreads();
            // phase 2: apply per-channel delay, pack 4 bytes/thread, coalesced write
            for (int idx = tid; idx < TT * 32; idx += 1024) {
                const int t = idx >> 5, w4 = idx & 31;
                uint32_t word = 0;
#pragma unroll
                for (int j = 0; j < 4; ++j) {
                    const int c = c0 + w4 * 4 + j;
                    const int ttt = t - dsh[c];
                    uint8_t byte = 0;
                    if (ttt >= 0 && (w4 * 4 + j) < w) byte = stage8[ttt * 128 + w4 * 4 + j];
                    word |= (uint32_t)byte << (8 * j);
                }
                outw[(size_t)t * (KP / 4) + (c0 >> 2) + w4] = word;
            }
        }
    } else if (blk < 288) {
        // ----- W_in per-row int8 quantization (warp per row) -----
        const int row = (blk - 256) * 32 + ty;
        float m = 0.0f;
        for (int c = tx; c < CC; c += 32) m = fmaxf(m, fabsf(Win[row * CC + c]));
#pragma unroll
        for (int off = 16; off; off >>= 1) m = fmaxf(m, __shfl_xor_sync(0xFFFFFFFFu, m, off));
        const float inv = (m > 0.0f) ? 127.0f / m : 0.0f;
        if (tx == 0) g_qscale[row] = m * (1.0f / 127.0f);
        for (int c = tx; c < KP; c += 32) {
            float wv = (c < CC) ? Win[row * CC + c] : 0.0f;
            g_Wq[row * KP + c] = (int8_t)__float2int_rn(wv * inv);
        }
    } else if (blk < 1312) {
        const int tI = blk - 288;
        const int tr = tI >> 5, tc = tI & 31;
        tile[ty][tx] = Wr1[(tr * 32 + ty) * H1 + tc * 32 + tx];
        __syncthreads();
        g_Wr1T[(tc * 32 + ty) * H1 + tr * 32 + tx] = tile[tx][ty];
    } else if (blk < 1824) {
        const int tI = blk - 1312;
        const int th = tI & 15, tj = tI >> 4;
        tile[ty][tx] = W2[(th * 32 + ty) * H1 + tj * 32 + tx];
        __syncthreads();
        g_W2T[(tj * 32 + ty) * H2 + th * 32 + tx] = tile[tx][ty];
    } else if (blk < 2080) {
        const int tI = blk - 1824;
        const int tr = tI >> 4, tc = tI & 15;
        tile[ty][tx] = Wr2[(tr * 32 + ty) * H2 + tc * 32 + tx];
        __syncthreads();
        g_Wr2T[(tc * 32 + ty) * H2 + tr * 32 + tx] = tile[tx][ty];
    } else {
        for (int i = tid; i < H2 * OO; i += 1024) {
            int j = i / OO, o = i % OO;
            g_WoT[i] = Wo[o * H2 + j];
        }
    }
}

// ---------------- K3: int8 IMMA GEMM, 4-stage cp.async (R9-proven) ----------------
#define BM 128
#define BN 128
#define BKK 32      // uint16 units per K-tile (= 64 int8)
#define SMSTR 40    // uint16 row stride (80B)
#define NSTG 4
#define GEMM_SMEM (NSTG * (BM + BN) * SMSTR * 2)   // 81920 bytes

#define CP_WAIT2()  asm volatile("cp.async.wait_group 2;\n" ::)

__global__ void __launch_bounds__(256, 2) k_gemm()
{
    extern __shared__ uint16_t smem[];
    uint16_t* Abase = smem;
    uint16_t* Bbase = smem + NSTG * BM * SMSTR;

    const int tid    = threadIdx.x;
    const int warpId = tid >> 5;
    const int lane   = tid & 31;
    const int g      = lane >> 2;
    const int t4     = lane & 3;

    const int row0 = blockIdx.y * BM;
    const int col0 = blockIdx.x * BN;
    const int wm   = (warpId & 1) * 64;
    const int wn   = (warpId >> 1) * 32;

    const int lrow0 = tid >> 2;
    const int lseg  = (tid & 3) * 8;   // uint16 units

    const uint16_t* Ag = reinterpret_cast<const uint16_t*>(g_xd8) + (size_t)row0 * KP16;
    const uint16_t* Bg = reinterpret_cast<const uint16_t*>(g_Wq)  + (size_t)col0 * KP16;

    uint32_t sA[NSTG], sB[NSTG];
#pragma unroll
    for (int s = 0; s < NSTG; ++s) {
        sA[s] = (uint32_t)__cvta_generic_to_shared(Abase + s * BM * SMSTR);
        sB[s] = (uint32_t)__cvta_generic_to_shared(Bbase + s * BN * SMSTR);
    }

    const int aoff = ((wm + (lane & 15)) * SMSTR + (lane >> 4) * 8) * 2;
    const int boff = ((wn + (lane & 7) + ((lane >> 4) << 3)) * SMSTR + ((lane >> 3) & 1) * 8) * 2;

    int acc[4][4][4];
#pragma unroll
    for (int i = 0; i < 4; ++i)
#pragma unroll
        for (int j = 0; j < 4; ++j)
#pragma unroll
            for (int c = 0; c < 4; ++c) acc[i][j][c] = 0;

    const int NK = KP16 / BKK;   // 11

#pragma unroll
    for (int s = 0; s < 3; ++s) {
        const int k0 = s * BKK;
        CP_ASYNC16(sA[s] + (lrow0 * SMSTR + lseg) * 2,        Ag + (size_t)lrow0 * KP16 + k0 + lseg);
        CP_ASYNC16(sA[s] + ((lrow0 + 64) * SMSTR + lseg) * 2, Ag + (size_t)(lrow0 + 64) * KP16 + k0 + lseg);
        CP_ASYNC16(sB[s] + (lrow0 * SMSTR + lseg) * 2,        Bg + (size_t)lrow0 * KP16 + k0 + lseg);
        CP_ASYNC16(sB[s] + ((lrow0 + 64) * SMSTR + lseg) * 2, Bg + (size_t)(lrow0 + 64) * KP16 + k0 + lseg);
        CP_COMMIT();
    }

    for (int kt = 0; kt < NK; ++kt) {
        const int st = kt & 3;
        CP_WAIT2();
        __syncthreads();

        if (kt + 3 < NK) {
            const int s = (kt + 3) & 3;
            const int k0 = (kt + 3) * BKK;
            CP_ASYNC16(sA[s] + (lrow0 * SMSTR + lseg) * 2,        Ag + (size_t)lrow0 * KP16 + k0 + lseg);
            CP_ASYNC16(sA[s] + ((lrow0 + 64) * SMSTR + lseg) * 2, Ag + (size_t)(lrow0 + 64) * KP16 + k0 + lseg);
            CP_ASYNC16(sB[s] + (lrow0 * SMSTR + lseg) * 2,        Bg + (size_t)lrow0 * KP16 + k0 + lseg);
            CP_ASYNC16(sB[s] + ((lrow0 + 64) * SMSTR + lseg) * 2, Bg + (size_t)(lrow0 + 64) * KP16 + k0 + lseg);
        }
        CP_COMMIT();

        const uint32_t aBase = sA[st] + aoff;
        const uint32_t bBase = sB[st] + boff;
#pragma unroll
        for (int ks = 0; ks < BKK; ks += 16) {
            uint32_t af[4][4];
            uint32_t bq[2][4];
#pragma unroll
            for (int i = 0; i < 4; ++i) {
                asm volatile("ldmatrix.sync.aligned.m8n8.x4.shared.b16 {%0,%1,%2,%3}, [%4];"
                             : "=r"(af[i][0]), "=r"(af[i][1]), "=r"(af[i][2]), "=r"(af[i][3])
                             : "r"(aBase + (i * 16 * SMSTR + ks) * 2));
            }
#pragma unroll
            for (int j2 = 0; j2 < 2; ++j2) {
                asm volatile("ldmatrix.sync.aligned.m8n8.x4.shared.b16 {%0,%1,%2,%3}, [%4];"
                             : "=r"(bq[j2][0]), "=r"(bq[j2][1]), "=r"(bq[j2][2]), "=r"(bq[j2][3])
                             : "r"(bBase + (j2 * 16 * SMSTR + ks) * 2));
            }
#pragma unroll
            for (int i = 0; i < 4; ++i)
#pragma unroll
                for (int j = 0; j < 4; ++j) {
                    const uint32_t b0 = bq[j >> 1][(j & 1) * 2];
                    const uint32_t b1 = bq[j >> 1][(j & 1) * 2 + 1];
                    asm volatile(
                        "mma.sync.aligned.m16n8k32.row.col.s32.s8.s8.s32 "
                        "{%0,%1,%2,%3}, {%4,%5,%6,%7}, {%8,%9}, {%0,%1,%2,%3};\n"
                        : "+r"(acc[i][j][0]), "+r"(acc[i][j][1]),
                          "+r"(acc[i][j][2]), "+r"(acc[i][j][3])
                        : "r"(af[i][0]), "r"(af[i][1]), "r"(af[i][2]), "r"(af[i][3]),
                          "r"(b0), "r"(b1));
                }
        }
    }

    // epilogue: dequantize with per-column scale, write bf16
#pragma unroll
    for (int j = 0; j < 4; ++j) {
        const int c = col0 + wn + j * 8 + 2 * t4;
        const float sc0 = g_qscale[c];
        const float sc1 = g_qscale[c + 1];
#pragma unroll
        for (int i = 0; i < 4; ++i) {
            const int r0 = row0 + wm + i * 16 + g;
            __nv_bfloat162 p0 = __float22bfloat162_rn(
                make_float2(sc0 * (float)acc[i][j][0], sc1 * (float)acc[i][j][1]));
            __nv_bfloat162 p1 = __float22bfloat162_rn(
                make_float2(sc0 * (float)acc[i][j][2], sc1 * (float)acc[i][j][3]));
            *reinterpret_cast<__nv_bfloat162*>(&g_IinB[(size_t)r0 * H1 + c])       = p0;
            *reinterpret_cast<__nv_bfloat162*>(&g_IinB[(size_t)(r0 + 8) * H1 + c]) = p1;
        }
    }
}

// ---------------- K4: recurrent scan — cp.async I_in ring (15 deep), 2 barriers/step ----------------
#define RSLOTS 16
#define RDEPTH 15

__global__ void __launch_bounds__(128) k_scan(
    const float* __restrict__ alpha1, const float* __restrict__ rho1, const float* __restrict__ beta_a1,
    const float* __restrict__ alpha2, const float* __restrict__ rho2, const float* __restrict__ beta_a2,
    const float* __restrict__ beta_out, float* __restrict__ out)
{
    __shared__ int cnt1[2], cnt2[2];
    __shared__ int act1[2][H1];
    __shared__ int act2[2][H2];
    __shared__ uint4 ring[RSLOTS][128];   // 32KB

    const int b   = blockIdx.x;
    const int tid = threadIdx.x;
    const int h0  = 8 * tid;
    const int h2  = 4 * tid;

    float alc1[8], rc1[8], bac1[8], v1[8], a1[8], s1[8];
#pragma unroll
    for (int k = 0; k < 2; ++k) {
        const float4 a = *(const float4*)&alpha1[h0 + 4 * k];
        const float4 r = *(const float4*)&rho1[h0 + 4 * k];
        const float4 bb = *(const float4*)&beta_a1[h0 + 4 * k];
        alc1[4*k] = a.x; alc1[4*k+1] = a.y; alc1[4*k+2] = a.z; alc1[4*k+3] = a.w;
        rc1[4*k] = r.x; rc1[4*k+1] = r.y; rc1[4*k+2] = r.z; rc1[4*k+3] = r.w;
        bac1[4*k] = bb.x; bac1[4*k+1] = bb.y; bac1[4*k+2] = bb.z; bac1[4*k+3] = bb.w;
    }
#pragma unroll
    for (int c = 0; c < 8; ++c) { v1[c] = 0.f; a1[c] = 0.f; s1[c] = 0.f; }

    float alc2[4], rc2[4], bac2[4], v2[4], a2[4], s2[4];
    {
        const float4 a = *(const float4*)&alpha2[h2];
        const float4 r = *(const float4*)&rho2[h2];
        const float4 bb = *(const float4*)&beta_a2[h2];
        alc2[0] = a.x; alc2[1] = a.y; alc2[2] = a.z; alc2[3] = a.w;
        rc2[0] = r.x; rc2[1] = r.y; rc2[2] = r.z; rc2[3] = r.w;
        bac2[0] = bb.x; bac2[1] = bb.y; bac2[2] = bb.z; bac2[3] = bb.w;
    }
#pragma unroll
    for (int c = 0; c < 4; ++c) { v2[c] = 0.f; a2[c] = 0.f; s2[c] = 0.f; }

    float bo = 0.f, obo = 0.f, vo = 0.f, vos = 0.f;
    if (tid < OO) { bo = beta_out[tid]; obo = 1.0f - bo; }

    if (tid == 0) { cnt1[0] = cnt1[1] = 0; cnt2[0] = cnt2[1] = 0; }
    __syncthreads();

    const uint4* Ibg = reinterpret_cast<const uint4*>(g_IinB + (size_t)b * TT * H1) + tid;
    const uint32_t ringAddr = (uint32_t)__cvta_generic_to_shared(&ring[0][tid]);

    // prologue: fill 15 slots
#pragma unroll
    for (int s = 0; s < RDEPTH; ++s) {
        CP_ASYNC16(ringAddr + s * (128 * 16), Ibg + (size_t)s * (H1 / 8));
        CP_COMMIT();
    }

    int p = 0;
    for (int t = 0; t < TT; ++t) {
        asm volatile("cp.async.wait_group 14;\n" ::);
        const uint4 packed = ring[t & (RSLOTS - 1)][tid];
        {
            const int tn = t + RDEPTH;
            if (tn < TT)
                CP_ASYNC16(ringAddr + (tn & (RSLOTS - 1)) * (128 * 16), Ibg + (size_t)tn * (H1 / 8));
            CP_COMMIT();
        }

        float I1[8];
        {
            const uint32_t pw[4] = {packed.x, packed.y, packed.z, packed.w};
#pragma unroll
            for (int k = 0; k < 4; ++k) {
                const __nv_bfloat162 bp = *reinterpret_cast<const __nv_bfloat162*>(&pw[k]);
                I1[2*k]   = __low2float(bp);
                I1[2*k+1] = __high2float(bp);
            }
        }

        const int q = p ^ 1;
        // ---- phase A: layer-1 update (reads act1[p]); reset cnt1[q]
        if (tid == 0) cnt1[q] = 0;
        const int n1 = cnt1[p];
        for (int i = 0; i < n1; ++i) {
            const float* wr = &g_Wr1T[act1[p][i] * H1 + h0];
            const float4 w0 = *(const float4*)wr;
            const float4 w1 = *(const float4*)(wr + 4);
            I1[0] += w0.x; I1[1] += w0.y; I1[2] += w0.z; I1[3] += w0.w;
            I1[4] += w1.x; I1[5] += w1.y; I1[6] += w1.z; I1[7] += w1.w;
        }
        float ns1[8];
#pragma unroll
        for (int c = 0; c < 8; ++c) {
            v1[c] = alc1[c] * v1[c] + (1.0f - alc1[c]) * I1[c] - s1[c] - a1[c];
            ns1[c] = (v1[c] >= 1.0f) ? 1.0f : 0.0f;
            a1[c] = rc1[c] * a1[c] + bac1[c] * ns1[c];
            s1[c] = ns1[c];
        }
        __syncthreads();                                 // B1

        // ---- phase B: publish layer-1 spikes; reset cnt2[q]
        if (tid == 1) cnt2[q] = 0;
#pragma unroll
        for (int c = 0; c < 8; ++c)
            if (ns1[c] != 0.0f) { int idx = atomicAdd(&cnt1[q], 1); act1[q][idx] = h0 + c; }
        __syncthreads();                                 // B2

        // ---- phase C: layer-2 update + deferred readout of step t-1
        {
            float I2[4] = {0.f, 0.f, 0.f, 0.f};
            const int m1 = cnt1[q];
            for (int i = 0; i < m1; ++i) {
                const float4 w = *(const float4*)&g_W2T[act1[q][i] * H2 + h2];
                I2[0] += w.x; I2[1] += w.y; I2[2] += w.z; I2[3] += w.w;
            }
            const int n2 = cnt2[p];
            for (int i = 0; i < n2; ++i) {
                const float4 w = *(const float4*)&g_Wr2T[act2[p][i] * H2 + h2];
                I2[0] += w.x; I2[1] += w.y; I2[2] += w.z; I2[3] += w.w;
            }
            float ns2[4];
#pragma unroll
            for (int c = 0; c < 4; ++c) {
                v2[c] = alc2[c] * v2[c] + (1.0f - alc2[c]) * I2[c] - s2[c] - a2[c];
                ns2[c] = (v2[c] >= 1.0f) ? 1.0f : 0.0f;
                a2[c] = rc2[c] * a2[c] + bac2[c] * ns2[c];
                s2[c] = ns2[c];
            }
#pragma unroll
            for (int c = 0; c < 4; ++c)
                if (ns2[c] != 0.0f) { int idx = atomicAdd(&cnt2[q], 1); act2[q][idx] = h2 + c; }
        }
        if (tid < OO && t > 0) {
            float Io = 0.f;
            const int m2 = cnt2[p];
            for (int i = 0; i < m2; ++i) Io += g_WoT[act2[p][i] * OO + tid];
            vo = bo * vo + obo * Io;
            vos += vo;
        }
        p = q;
    }

    __syncthreads();
    if (tid < OO) {
        float Io = 0.f;
        const int m2 = cnt2[p];
        for (int i = 0; i < m2; ++i) Io += g_WoT[act2[p][i] * OO + tid];
        vo = bo * vo + obo * Io;
        vos += vo;
        out[b * OO + tid] = vos * (1.0f / (float)TT);
    }
}

// ---------------- launch ----------------
extern "C" void kernel_launch(void* const* d_in, const int* in_sizes, int n_in,
                              void* d_out, int out_size)
{
    const float* x       = (const float*)d_in[0];
    const int*   delays  = (const int*)  d_in[1];
    const float* W_in    = (const float*)d_in[2];
    const float* W_rec1  = (const float*)d_in[3];
    const float* W2      = (const float*)d_in[4];
    const float* W_rec2  = (const float*)d_in[5];
    const float* W_out   = (const float*)d_in[6];
    const float* alpha1  = (const float*)d_in[7];
    const float* rho1    = (const float*)d_in[8];
    const float* beta_a1 = (const float*)d_in[9];
    const float* alpha2  = (const float*)d_in[10];
    const float* rho2    = (const float*)d_in[11];
    const float* beta_a2 = (const float*)d_in[12];
    const float* beta_out= (const float*)d_in[13];
    float* out = (float*)d_out;

    static int smem_set = 0;
    if (!smem_set) {
        cudaFuncSetAttribute(k_gemm, cudaFuncAttributeMaxDynamicSharedMemorySize, GEMM_SMEM);
        smem_set = 1;
    }

    k_prep_build<<<PB_TOTAL, 1024>>>(x, delays, W_in, W_rec1, W2, W_rec2, W_out);

    {
        dim3 grid(H1 / BN, BT / BM);   // (8, 500)
        k_gemm<<<grid, 256, GEMM_SMEM>>>();
    }

    k_scan<<<BATCH, 128>>>(alpha1, rho1, beta_a1, alpha2, rho2, beta_a2, beta_out, out);
}